// round 2
// baseline (speedup 1.0000x reference)
#include <cuda_runtime.h>
#include <math.h>

// Problem constants
#define BB 8
#define SS 2048
#define DD 1024
#define AD 512

// Scratch (allocation-free rule: __device__ globals)
__device__ float g_q[BB * SS * AD];
__device__ float g_k[BB * SS * AD];
__device__ float g_v[BB * SS * AD];
__device__ float g_win[BB * SS * AD];
__device__ float g_scores[(size_t)BB * SS * SS];
__device__ float g_y[BB * SS * DD];
__device__ float g_gq[BB * AD];
__device__ float g_gs[BB * SS];
__device__ float g_gout[BB * AD];

// ---------------------------------------------------------------------------
// Tiled fp32 GEMM: C[M,N] = A[M,K] * B[K,N] (TB=false) or A[M,K]*B[N,K]^T (TB=true)
// 64x64 tile, BK=16, 256 threads, 4x4 per thread.
// EPI: 0 = +bias(e0[n]); 1 = *scale; 2 = 0.7*acc + 0.3*e0[z*AD+n];
//      3 = +e0[n] + e1[m*ldc+n] (bias + residual)
// ---------------------------------------------------------------------------
#define BM 64
#define BN 64
#define BK 16

template <bool TB, int EPI>
__global__ void __launch_bounds__(256) gemm_k(
    const float* __restrict__ Am, const float* __restrict__ Bm, float* __restrict__ Cm,
    int K, int lda, int ldb, int ldc,
    size_t sA, size_t sB, size_t sC,
    const float* __restrict__ e0, const float* __restrict__ e1, float scale)
{
    const float* Ap = Am + (size_t)blockIdx.z * sA;
    const float* Bp = Bm + (size_t)blockIdx.z * sB;
    float* Cp = Cm + (size_t)blockIdx.z * sC;

    __shared__ float As[BK][BM + 4];
    __shared__ float Bs[BK][BN + 4];

    int tid = threadIdx.x;
    int tx = tid & 15, ty = tid >> 4;
    int m0 = blockIdx.y * BM;
    int n0 = blockIdx.x * BN;

    int ar = tid >> 2;           // 0..63
    int ac = (tid & 3) << 2;     // 0,4,8,12
    int br = tid >> 4;           // 0..15 (NN)
    int bc = (tid & 15) << 2;    // 0..60 (NN)

    float acc[4][4];
#pragma unroll
    for (int i = 0; i < 4; i++)
#pragma unroll
        for (int j = 0; j < 4; j++) acc[i][j] = 0.f;

    for (int k0 = 0; k0 < K; k0 += BK) {
        float4 va = *(const float4*)(Ap + (size_t)(m0 + ar) * lda + k0 + ac);
        As[ac + 0][ar] = va.x; As[ac + 1][ar] = va.y;
        As[ac + 2][ar] = va.z; As[ac + 3][ar] = va.w;
        if (TB) {
            float4 vb = *(const float4*)(Bp + (size_t)(n0 + ar) * ldb + k0 + ac);
            Bs[ac + 0][ar] = vb.x; Bs[ac + 1][ar] = vb.y;
            Bs[ac + 2][ar] = vb.z; Bs[ac + 3][ar] = vb.w;
        } else {
            float4 vb = *(const float4*)(Bp + (size_t)(k0 + br) * ldb + n0 + bc);
            *(float4*)&Bs[br][bc] = vb;
        }
        __syncthreads();
#pragma unroll
        for (int k = 0; k < BK; k++) {
            float4 a4 = *(const float4*)&As[k][ty << 2];
            float4 b4 = *(const float4*)&Bs[k][tx << 2];
            float av4[4] = {a4.x, a4.y, a4.z, a4.w};
            float bv4[4] = {b4.x, b4.y, b4.z, b4.w};
#pragma unroll
            for (int i = 0; i < 4; i++)
#pragma unroll
                for (int j = 0; j < 4; j++) acc[i][j] += av4[i] * bv4[j];
        }
        __syncthreads();
    }

#pragma unroll
    for (int i = 0; i < 4; i++) {
        int m = m0 + (ty << 2) + i;
#pragma unroll
        for (int j = 0; j < 4; j++) {
            int n = n0 + (tx << 2) + j;
            float v = acc[i][j];
            if (EPI == 0) v += e0[n];
            else if (EPI == 1) v *= scale;
            else if (EPI == 2) v = 0.7f * v + 0.3f * e0[blockIdx.z * AD + n];
            else if (EPI == 3) v += e0[n] + e1[(size_t)m * ldc + n];
            Cp[(size_t)m * ldc + n] = v;
        }
    }
}

// ---------------------------------------------------------------------------
// gq[b,a] = bq[a] + dot(gc[b,:], Wq[:,a])
// grid (AD/128, BB), 128 threads
// ---------------------------------------------------------------------------
__global__ void __launch_bounds__(128) k_gq(
    const float* __restrict__ gc, const float* __restrict__ W,
    const float* __restrict__ bias, float* __restrict__ out)
{
    int a = blockIdx.x * 128 + threadIdx.x;
    int b = blockIdx.y;
    float s = 0.f;
    const float* g = gc + (size_t)b * DD;
    for (int d = 0; d < DD; d++) s += g[d] * W[(size_t)d * AD + a];
    out[b * AD + a] = s + bias[a];
}

// ---------------------------------------------------------------------------
// gscores[b,s] = dot(gq[b,:], k[b,s,:]) / sqrt(AD).  8 lanes per key.
// grid BB*SS/32, 256 threads
// ---------------------------------------------------------------------------
__global__ void __launch_bounds__(256) k_gscores(
    const float* __restrict__ kp, const float* __restrict__ gq, float* __restrict__ gs)
{
    int t = threadIdx.x;
    int key = blockIdx.x * 32 + (t >> 3);
    int lane = t & 7;
    int b = key / SS;
    int s = key % SS;
    const float* krow = kp + (size_t)key * AD;
    const float* q = gq + b * AD;
    float sum = 0.f;
    for (int a = lane; a < AD; a += 8) sum += krow[a] * q[a];
#pragma unroll
    for (int o = 4; o > 0; o >>= 1) sum += __shfl_down_sync(0xffffffffu, sum, o, 8);
    if (lane == 0) gs[b * SS + s] = sum * rsqrtf((float)AD);
}

// ---------------------------------------------------------------------------
// Row softmax, ncols = SS, 256 threads per row
// ---------------------------------------------------------------------------
__global__ void __launch_bounds__(256) k_softmax(float* __restrict__ data)
{
    float* row = data + (size_t)blockIdx.x * SS;
    int t = threadIdx.x;
    __shared__ float red1[8], red2[8];

    float m = -3.4e38f;
    for (int i = t; i < SS; i += 256) m = fmaxf(m, row[i]);
#pragma unroll
    for (int o = 16; o > 0; o >>= 1) m = fmaxf(m, __shfl_xor_sync(0xffffffffu, m, o));
    if ((t & 31) == 0) red1[t >> 5] = m;
    __syncthreads();
    m = red1[0];
#pragma unroll
    for (int w = 1; w < 8; w++) m = fmaxf(m, red1[w]);

    float s = 0.f;
    for (int i = t; i < SS; i += 256) {
        float e = __expf(row[i] - m);
        row[i] = e;
        s += e;
    }
#pragma unroll
    for (int o = 16; o > 0; o >>= 1) s += __shfl_xor_sync(0xffffffffu, s, o);
    if ((t & 31) == 0) red2[t >> 5] = s;
    __syncthreads();
    float tot = 0.f;
#pragma unroll
    for (int w = 0; w < 8; w++) tot += red2[w];
    float inv = 1.f / tot;
    for (int i = t; i < SS; i += 256) row[i] *= inv;
}

// ---------------------------------------------------------------------------
// global_out[b,a] = sum_s gw[b,s] * v[b,s,a].  grid (AD/128, BB)
// ---------------------------------------------------------------------------
__global__ void __launch_bounds__(128) k_gout(
    const float* __restrict__ gw, const float* __restrict__ vp, float* __restrict__ go)
{
    int a = blockIdx.x * 128 + threadIdx.x;
    int b = blockIdx.y;
    float sum = 0.f;
    const float* vb = vp + (size_t)b * SS * AD;
    const float* w = gw + b * SS;
    for (int s = 0; s < SS; s++) sum += w[s] * vb[(size_t)s * AD + a];
    go[b * AD + a] = sum;
}

// ---------------------------------------------------------------------------
// LayerNorm in-place on g_y rows (len DD). grid BB*SS, 256 threads.
// ---------------------------------------------------------------------------
__global__ void __launch_bounds__(256) k_ln(
    float* __restrict__ y, const float* __restrict__ gamma, const float* __restrict__ beta)
{
    float* row = y + (size_t)blockIdx.x * DD;
    int t = threadIdx.x;
    float v[4], sum = 0.f, sq = 0.f;
#pragma unroll
    for (int i = 0; i < 4; i++) {
        v[i] = row[t + 256 * i];
        sum += v[i];
        sq += v[i] * v[i];
    }
    __shared__ float r1[8], r2[8];
#pragma unroll
    for (int o = 16; o > 0; o >>= 1) {
        sum += __shfl_xor_sync(0xffffffffu, sum, o);
        sq += __shfl_xor_sync(0xffffffffu, sq, o);
    }
    if ((t & 31) == 0) { r1[t >> 5] = sum; r2[t >> 5] = sq; }
    __syncthreads();
    float ts = 0.f, tq = 0.f;
#pragma unroll
    for (int w = 0; w < 8; w++) { ts += r1[w]; tq += r2[w]; }
    float mu = ts * (1.f / DD);
    float var = tq * (1.f / DD) - mu * mu;
    float inv = rsqrtf(var + 1e-5f);
#pragma unroll
    for (int i = 0; i < 4; i++) {
        int c = t + 256 * i;
        row[c] = (v[i] - mu) * inv * gamma[c] + beta[c];
    }
}

// ---------------------------------------------------------------------------
// avg_w[b,s] = 0.7 * mean_q weights[b,q,s] + 0.3 * gw[b,s].  grid (SS/256, BB)
// ---------------------------------------------------------------------------
__global__ void __launch_bounds__(256) k_colmean(
    const float* __restrict__ wts, const float* __restrict__ gw, float* __restrict__ avg)
{
    int s = blockIdx.x * 256 + threadIdx.x;
    int b = blockIdx.y;
    const float* base = wts + (size_t)b * SS * SS + s;
    float sum = 0.f;
    for (int q = 0; q < SS; q++) sum += base[(size_t)q * SS];
    avg[b * SS + s] = 0.7f * (sum * (1.f / SS)) + 0.3f * gw[b * SS + s];
}

// ---------------------------------------------------------------------------
// context[b,d] = sum_s avg_w[b,s] * y_ln[b,s,d].  grid (DD/256, BB)
// ---------------------------------------------------------------------------
__global__ void __launch_bounds__(256) k_context(
    const float* __restrict__ avg, const float* __restrict__ y, float* __restrict__ ctx)
{
    int d = blockIdx.x * 256 + threadIdx.x;
    int b = blockIdx.y;
    const float* yb = y + (size_t)b * SS * DD;
    const float* w = avg + b * SS;
    float sum = 0.f;
    for (int s = 0; s < SS; s++) sum += w[s] * yb[(size_t)s * DD + d];
    ctx[b * DD + d] = sum;
}

// ---------------------------------------------------------------------------

extern "C" void kernel_launch(void* const* d_in, const int* in_sizes, int n_in,
                              void* d_out, int out_size)
{
    const float* x     = (const float*)d_in[0];
    const float* gc    = (const float*)d_in[1];
    const float* Wq    = (const float*)d_in[2];
    const float* bq    = (const float*)d_in[3];
    const float* Wk    = (const float*)d_in[4];
    const float* bk    = (const float*)d_in[5];
    const float* Wv    = (const float*)d_in[6];
    const float* bv    = (const float*)d_in[7];
    const float* Wo    = (const float*)d_in[8];
    const float* bo    = (const float*)d_in[9];
    const float* gamma = (const float*)d_in[10];
    const float* beta  = (const float*)d_in[11];
    float* outp = (float*)d_out;

    float *pq, *pk, *pv, *pwin, *psc, *py, *pgq, *pgs, *pgo;
    cudaGetSymbolAddress((void**)&pq,  g_q);
    cudaGetSymbolAddress((void**)&pk,  g_k);
    cudaGetSymbolAddress((void**)&pv,  g_v);
    cudaGetSymbolAddress((void**)&pwin, g_win);
    cudaGetSymbolAddress((void**)&psc, g_scores);
    cudaGetSymbolAddress((void**)&py,  g_y);
    cudaGetSymbolAddress((void**)&pgq, g_gq);
    cudaGetSymbolAddress((void**)&pgs, g_gs);
    cudaGetSymbolAddress((void**)&pgo, g_gout);

    const float scl = 1.0f / sqrtf((float)AD);
    const size_t strBSA = (size_t)SS * AD;   // per-batch q/k/v stride
    const size_t strBSS = (size_t)SS * SS;   // per-batch scores stride

    // Q, K, V projections: [16384,1024] x [1024,512] + bias
    gemm_k<false, 0><<<dim3(AD / BN, (BB * SS) / BM, 1), 256>>>(
        x, Wq, pq, DD, DD, AD, AD, 0, 0, 0, bq, nullptr, 0.f);
    gemm_k<false, 0><<<dim3(AD / BN, (BB * SS) / BM, 1), 256>>>(
        x, Wk, pk, DD, DD, AD, AD, 0, 0, 0, bk, nullptr, 0.f);
    gemm_k<false, 0><<<dim3(AD / BN, (BB * SS) / BM, 1), 256>>>(
        x, Wv, pv, DD, DD, AD, AD, 0, 0, 0, bv, nullptr, 0.f);

    // global query projection
    k_gq<<<dim3(AD / 128, BB), 128>>>(gc, Wq, bq, pgq);

    // scores = q @ k^T / sqrt(A)   (per batch, NT)
    gemm_k<true, 1><<<dim3(SS / BN, SS / BM, BB), 256>>>(
        pq, pk, psc, AD, AD, AD, SS, strBSA, strBSA, strBSS, nullptr, nullptr, scl);

    // softmax over each of 16384 rows
    k_softmax<<<BB * SS, 256>>>(psc);

    // global scores + softmax
    k_gscores<<<(BB * SS) / 32, 256>>>(pk, pgq, pgs);
    k_softmax<<<BB, 256>>>(pgs);

    // global_out
    k_gout<<<dim3(AD / 128, BB), 128>>>(pgs, pv, pgo);

    // win_out = 0.7 * weights@v + 0.3 * global_out   (per batch, NN)
    gemm_k<false, 2><<<dim3(AD / BN, SS / BM, BB), 256>>>(
        psc, pv, pwin, SS, SS, AD, AD, strBSS, strBSA, strBSA, pgo, nullptr, 0.f);

    // y = x + win_out @ Wo + bo
    gemm_k<false, 3><<<dim3(DD / BN, (BB * SS) / BM, 1), 256>>>(
        pwin, Wo, py, AD, AD, DD, DD, 0, 0, 0, bo, x, 0.f);

    // LayerNorm in place
    k_ln<<<BB * SS, 256>>>(py, gamma, beta);

    // avg_w -> d_out[8192:], context -> d_out[:8192]
    k_colmean<<<dim3(SS / 256, BB), 256>>>(psc, pgs, outp + BB * DD);
    k_context<<<dim3(DD / 256, BB), 256>>>(outp + BB * DD, py, outp);
}

// round 3
// speedup vs baseline: 2.7377x; 2.7377x over previous
#include <cuda_runtime.h>
#include <math.h>
#include <stdint.h>

// Problem constants
#define BB 8
#define SS 2048
#define DD 1024
#define AD 512

// Scratch (allocation-free rule: __device__ globals)
__device__ float g_q[BB * SS * AD];
__device__ float g_k[BB * SS * AD];
__device__ float g_v[BB * SS * AD];
__device__ float g_win[BB * SS * AD];
__device__ float g_scores[(size_t)BB * SS * SS];
__device__ float g_y[BB * SS * DD];
__device__ float g_gq[BB * AD];
__device__ float g_gs[BB * SS];
__device__ float g_gout[BB * AD];
__device__ float g_part[BB * 16 * SS];   // reusable partial-sum scratch (1 MB)

// ---------------------------------------------------------------------------
// tf32 tensor-core GEMM.
// C[M,N] = A[M,K] * B[K,N] (TB=false) or A[M,K] * B[N,K]^T (TB=true)
// Tile: 128x128x16, 256 threads (8 warps as 4m x 2n, each warp 32x64).
// mma.sync.m16n8k8.tf32, cp.async double buffering.
// EPI: 0 = +e0[n]; 1 = *scale; 2 = 0.7*acc + 0.3*e0[z*AD+n];
//      3 = +e0[n] + e1[m*ldc+n]
// ---------------------------------------------------------------------------
#define TFBM 128
#define TFBN 128
#define TFBK 16
#define ASTR 20    // TFBK+4 floats (80B, 16B-multiple, conflict-free frags)
#define BSTR 132   // TFBN+4 floats (528B, 16B-multiple)

__device__ __forceinline__ void cp16(void* s, const void* g) {
    uint32_t sa = (uint32_t)__cvta_generic_to_shared(s);
    asm volatile("cp.async.cg.shared.global [%0], [%1], 16;\n" :: "r"(sa), "l"(g));
}
__device__ __forceinline__ uint32_t f2tf(float f) {
    uint32_t u;
    asm("cvt.rna.tf32.f32 %0, %1;" : "=r"(u) : "f"(f));
    return u;
}

template <bool TB, int EPI>
__global__ void __launch_bounds__(256) gemm_tf32(
    const float* __restrict__ Am, const float* __restrict__ Bm, float* __restrict__ Cm,
    int K, int lda, int ldb, int ldc,
    size_t sA, size_t sB, size_t sC,
    const float* __restrict__ e0, const float* __restrict__ e1, float scale)
{
    const float* Ap = Am + (size_t)blockIdx.z * sA;
    const float* Bp = Bm + (size_t)blockIdx.z * sB;
    float* Cp = Cm + (size_t)blockIdx.z * sC;

    // A always stored row-major [128][ASTR]. B: NN -> [16][BSTR], NT -> [128][ASTR].
    __shared__ float As[2][TFBM * ASTR];
    __shared__ float Bs[2][TB ? (TFBM * ASTR) : (TFBK * BSTR)];

    const int tid = threadIdx.x;
    const int wid = tid >> 5;
    const int lane = tid & 31;
    const int wm = wid >> 1;       // 0..3  -> 32 rows each
    const int wn = wid & 1;        // 0..1  -> 64 cols each
    const int g = lane >> 2;       // group 0..7
    const int t = lane & 3;        // 0..3
    const int m0 = blockIdx.y * TFBM;
    const int n0 = blockIdx.x * TFBN;

    float acc[2][8][4];
#pragma unroll
    for (int i = 0; i < 2; i++)
#pragma unroll
        for (int j = 0; j < 8; j++)
#pragma unroll
            for (int c = 0; c < 4; c++) acc[i][j][c] = 0.f;

    auto copy_stage = [&](int st, int k0) {
        // A tile: 128 rows x 4 quads = 512 chunks, 2 per thread
#pragma unroll
        for (int i = 0; i < 2; i++) {
            int c = tid + 256 * i;
            int row = c >> 2, q = (c & 3) << 2;
            cp16(&As[st][row * ASTR + q], Ap + (size_t)(m0 + row) * lda + k0 + q);
        }
        if (TB) {
#pragma unroll
            for (int i = 0; i < 2; i++) {
                int c = tid + 256 * i;
                int row = c >> 2, q = (c & 3) << 2;
                cp16(&Bs[st][row * ASTR + q], Bp + (size_t)(n0 + row) * ldb + k0 + q);
            }
        } else {
#pragma unroll
            for (int i = 0; i < 2; i++) {
                int c = tid + 256 * i;
                int row = c >> 5, q = (c & 31) << 2;
                cp16(&Bs[st][row * BSTR + q], Bp + (size_t)(k0 + row) * ldb + n0 + q);
            }
        }
    };

    copy_stage(0, 0);
    asm volatile("cp.async.commit_group;\n");
    asm volatile("cp.async.wait_group 0;\n");
    __syncthreads();

    const int nk = K / TFBK;
    for (int kt = 0; kt < nk; kt++) {
        int cur = kt & 1, nxt = cur ^ 1;
        if (kt + 1 < nk) {
            copy_stage(nxt, (kt + 1) * TFBK);
            asm volatile("cp.async.commit_group;\n");
        }
#pragma unroll
        for (int ks = 0; ks < 2; ks++) {
            const int kb = ks * 8;
            // A fragments: 2 m-tiles
            uint32_t afr[2][4];
#pragma unroll
            for (int mt = 0; mt < 2; mt++) {
                int r = wm * 32 + mt * 16 + g;
                const float* ab = &As[cur][0];
                afr[mt][0] = f2tf(ab[(r)     * ASTR + kb + t]);
                afr[mt][1] = f2tf(ab[(r + 8) * ASTR + kb + t]);
                afr[mt][2] = f2tf(ab[(r)     * ASTR + kb + t + 4]);
                afr[mt][3] = f2tf(ab[(r + 8) * ASTR + kb + t + 4]);
            }
#pragma unroll
            for (int nt = 0; nt < 8; nt++) {
                int n = wn * 64 + nt * 8 + g;
                uint32_t b0, b1;
                if (TB) {
                    b0 = f2tf(Bs[cur][n * ASTR + kb + t]);
                    b1 = f2tf(Bs[cur][n * ASTR + kb + t + 4]);
                } else {
                    b0 = f2tf(Bs[cur][(kb + t) * BSTR + n]);
                    b1 = f2tf(Bs[cur][(kb + t + 4) * BSTR + n]);
                }
#pragma unroll
                for (int mt = 0; mt < 2; mt++) {
                    asm volatile(
                        "mma.sync.aligned.m16n8k8.row.col.f32.tf32.tf32.f32 "
                        "{%0,%1,%2,%3}, {%4,%5,%6,%7}, {%8,%9}, {%0,%1,%2,%3};\n"
                        : "+f"(acc[mt][nt][0]), "+f"(acc[mt][nt][1]),
                          "+f"(acc[mt][nt][2]), "+f"(acc[mt][nt][3])
                        : "r"(afr[mt][0]), "r"(afr[mt][1]), "r"(afr[mt][2]), "r"(afr[mt][3]),
                          "r"(b0), "r"(b1));
                }
            }
        }
        if (kt + 1 < nk) asm volatile("cp.async.wait_group 0;\n");
        __syncthreads();
    }

    // Epilogue
#pragma unroll
    for (int mt = 0; mt < 2; mt++) {
#pragma unroll
        for (int nt = 0; nt < 8; nt++) {
            int row = m0 + wm * 32 + mt * 16 + g;
            int col = n0 + wn * 64 + nt * 8 + t * 2;
#pragma unroll
            for (int h = 0; h < 2; h++) {
                int r = row + h * 8;
                float v0 = acc[mt][nt][h * 2 + 0];
                float v1 = acc[mt][nt][h * 2 + 1];
                if (EPI == 0) { v0 += e0[col]; v1 += e0[col + 1]; }
                else if (EPI == 1) { v0 *= scale; v1 *= scale; }
                else if (EPI == 2) {
                    v0 = 0.7f * v0 + 0.3f * e0[blockIdx.z * AD + col];
                    v1 = 0.7f * v1 + 0.3f * e0[blockIdx.z * AD + col + 1];
                } else if (EPI == 3) {
                    v0 += e0[col]     + e1[(size_t)r * ldc + col];
                    v1 += e0[col + 1] + e1[(size_t)r * ldc + col + 1];
                }
                *(float2*)&Cp[(size_t)r * ldc + col] = make_float2(v0, v1);
            }
        }
    }
}

// ---------------------------------------------------------------------------
// gq two-stage: part[b][dc][a] then reduce with bias
// ---------------------------------------------------------------------------
__global__ void __launch_bounds__(128) k_gq_part(
    const float* __restrict__ gc, const float* __restrict__ W, float* __restrict__ part)
{
    int a = blockIdx.x * 128 + threadIdx.x;
    int dc = blockIdx.y, b = blockIdx.z;
    const float* gv = gc + (size_t)b * DD + dc * 128;
    const float* Wp = W + (size_t)(dc * 128) * AD + a;
    float s = 0.f;
#pragma unroll 4
    for (int d = 0; d < 128; d++) s += gv[d] * Wp[(size_t)d * AD];
    part[((size_t)b * 8 + dc) * AD + a] = s;
}
__global__ void __launch_bounds__(128) k_gq_red(
    const float* __restrict__ part, const float* __restrict__ bias, float* __restrict__ gq)
{
    int a = blockIdx.x * 128 + threadIdx.x;
    int b = blockIdx.y;
    float s = bias[a];
#pragma unroll
    for (int j = 0; j < 8; j++) s += part[((size_t)b * 8 + j) * AD + a];
    gq[b * AD + a] = s;
}

// ---------------------------------------------------------------------------
// gscores[b,s] = dot(gq[b,:], k[b,s,:]) / sqrt(AD)
// ---------------------------------------------------------------------------
__global__ void __launch_bounds__(256) k_gscores(
    const float* __restrict__ kp, const float* __restrict__ gq, float* __restrict__ gs)
{
    int t = threadIdx.x;
    int key = blockIdx.x * 32 + (t >> 3);
    int lane = t & 7;
    int b = key / SS;
    int s = key % SS;
    const float* krow = kp + (size_t)key * AD;
    const float* q = gq + b * AD;
    float sum = 0.f;
    for (int a = lane; a < AD; a += 8) sum += krow[a] * q[a];
#pragma unroll
    for (int o = 4; o > 0; o >>= 1) sum += __shfl_down_sync(0xffffffffu, sum, o, 8);
    if (lane == 0) gs[b * SS + s] = sum * rsqrtf((float)AD);
}

// ---------------------------------------------------------------------------
// Row softmax over SS cols, 256 threads per row
// ---------------------------------------------------------------------------
__global__ void __launch_bounds__(256) k_softmax(float* __restrict__ data)
{
    float* row = data + (size_t)blockIdx.x * SS;
    int t = threadIdx.x;
    __shared__ float red1[8], red2[8];

    float m = -3.4e38f;
    for (int i = t; i < SS; i += 256) m = fmaxf(m, row[i]);
#pragma unroll
    for (int o = 16; o > 0; o >>= 1) m = fmaxf(m, __shfl_xor_sync(0xffffffffu, m, o));
    if ((t & 31) == 0) red1[t >> 5] = m;
    __syncthreads();
    m = red1[0];
#pragma unroll
    for (int w = 1; w < 8; w++) m = fmaxf(m, red1[w]);

    float s = 0.f;
    for (int i = t; i < SS; i += 256) {
        float e = __expf(row[i] - m);
        row[i] = e;
        s += e;
    }
#pragma unroll
    for (int o = 16; o > 0; o >>= 1) s += __shfl_xor_sync(0xffffffffu, s, o);
    if ((t & 31) == 0) red2[t >> 5] = s;
    __syncthreads();
    float tot = 0.f;
#pragma unroll
    for (int w = 0; w < 8; w++) tot += red2[w];
    float inv = 1.f / tot;
    for (int i = t; i < SS; i += 256) row[i] *= inv;
}

// ---------------------------------------------------------------------------
// global_out two-stage: part[b][sc(16)][a], reduce
// ---------------------------------------------------------------------------
__global__ void __launch_bounds__(128) k_gout_part(
    const float* __restrict__ gw, const float* __restrict__ vp, float* __restrict__ part)
{
    int a = blockIdx.x * 128 + threadIdx.x;
    int sc = blockIdx.y, b = blockIdx.z;
    const float* vb = vp + (size_t)b * SS * AD + (size_t)(sc * 128) * AD + a;
    const float* w = gw + b * SS + sc * 128;
    float sum = 0.f;
#pragma unroll 4
    for (int s = 0; s < 128; s++) sum += w[s] * vb[(size_t)s * AD];
    part[((size_t)b * 16 + sc) * AD + a] = sum;
}
__global__ void __launch_bounds__(128) k_gout_red(
    const float* __restrict__ part, float* __restrict__ go)
{
    int a = blockIdx.x * 128 + threadIdx.x;
    int b = blockIdx.y;
    float s = 0.f;
#pragma unroll
    for (int j = 0; j < 16; j++) s += part[((size_t)b * 16 + j) * AD + a];
    go[b * AD + a] = s;
}

// ---------------------------------------------------------------------------
// LayerNorm in-place on rows (len DD)
// ---------------------------------------------------------------------------
__global__ void __launch_bounds__(256) k_ln(
    float* __restrict__ y, const float* __restrict__ gamma, const float* __restrict__ beta)
{
    float* row = y + (size_t)blockIdx.x * DD;
    int t = threadIdx.x;
    float v[4], sum = 0.f, sq = 0.f;
#pragma unroll
    for (int i = 0; i < 4; i++) {
        v[i] = row[t + 256 * i];
        sum += v[i];
        sq += v[i] * v[i];
    }
    __shared__ float r1[8], r2[8];
#pragma unroll
    for (int o = 16; o > 0; o >>= 1) {
        sum += __shfl_xor_sync(0xffffffffu, sum, o);
        sq += __shfl_xor_sync(0xffffffffu, sq, o);
    }
    if ((t & 31) == 0) { r1[t >> 5] = sum; r2[t >> 5] = sq; }
    __syncthreads();
    float ts = 0.f, tq = 0.f;
#pragma unroll
    for (int w = 0; w < 8; w++) { ts += r1[w]; tq += r2[w]; }
    float mu = ts * (1.f / DD);
    float var = tq * (1.f / DD) - mu * mu;
    float inv = rsqrtf(var + 1e-5f);
#pragma unroll
    for (int i = 0; i < 4; i++) {
        int c = t + 256 * i;
        row[c] = (v[i] - mu) * inv * gamma[c] + beta[c];
    }
}

// ---------------------------------------------------------------------------
// colmean two-stage: part[b][qc(8)][s], reduce to avg_w
// ---------------------------------------------------------------------------
__global__ void __launch_bounds__(256) k_colmean_part(
    const float* __restrict__ wts, float* __restrict__ part)
{
    int s = blockIdx.x * 256 + threadIdx.x;
    int qc = blockIdx.y, b = blockIdx.z;
    const float* base = wts + (size_t)b * SS * SS + (size_t)(qc * 256) * SS + s;
    float sum = 0.f;
#pragma unroll 4
    for (int q = 0; q < 256; q++) sum += base[(size_t)q * SS];
    part[((size_t)b * 8 + qc) * SS + s] = sum;
}
__global__ void __launch_bounds__(256) k_colmean_red(
    const float* __restrict__ part, const float* __restrict__ gw, float* __restrict__ avg)
{
    int s = blockIdx.x * 256 + threadIdx.x;
    int b = blockIdx.y;
    float sum = 0.f;
#pragma unroll
    for (int j = 0; j < 8; j++) sum += part[((size_t)b * 8 + j) * SS + s];
    avg[b * SS + s] = 0.7f * (sum * (1.f / SS)) + 0.3f * gw[b * SS + s];
}

// ---------------------------------------------------------------------------
// context two-stage: part[b][sc(16)][d], reduce
// ---------------------------------------------------------------------------
__global__ void __launch_bounds__(256) k_context_part(
    const float* __restrict__ avg, const float* __restrict__ y, float* __restrict__ part)
{
    int d = blockIdx.x * 256 + threadIdx.x;
    int sc = blockIdx.y, b = blockIdx.z;
    const float* yb = y + (size_t)b * SS * DD + (size_t)(sc * 128) * DD + d;
    const float* w = avg + b * SS + sc * 128;
    float sum = 0.f;
#pragma unroll 4
    for (int s = 0; s < 128; s++) sum += w[s] * yb[(size_t)s * DD];
    part[((size_t)b * 16 + sc) * DD + d] = sum;
}
__global__ void __launch_bounds__(256) k_context_red(
    const float* __restrict__ part, float* __restrict__ ctx)
{
    int d = blockIdx.x * 256 + threadIdx.x;
    int b = blockIdx.y;
    float s = 0.f;
#pragma unroll
    for (int j = 0; j < 16; j++) s += part[((size_t)b * 16 + j) * DD + d];
    ctx[b * DD + d] = s;
}

// ---------------------------------------------------------------------------

extern "C" void kernel_launch(void* const* d_in, const int* in_sizes, int n_in,
                              void* d_out, int out_size)
{
    const float* x     = (const float*)d_in[0];
    const float* gc    = (const float*)d_in[1];
    const float* Wq    = (const float*)d_in[2];
    const float* bq    = (const float*)d_in[3];
    const float* Wk    = (const float*)d_in[4];
    const float* bk    = (const float*)d_in[5];
    const float* Wv    = (const float*)d_in[6];
    const float* bv    = (const float*)d_in[7];
    const float* Wo    = (const float*)d_in[8];
    const float* bo    = (const float*)d_in[9];
    const float* gamma = (const float*)d_in[10];
    const float* beta  = (const float*)d_in[11];
    float* outp = (float*)d_out;

    float *pq, *pk, *pv, *pwin, *psc, *py, *pgq, *pgs, *pgo, *ppart;
    cudaGetSymbolAddress((void**)&pq,  g_q);
    cudaGetSymbolAddress((void**)&pk,  g_k);
    cudaGetSymbolAddress((void**)&pv,  g_v);
    cudaGetSymbolAddress((void**)&pwin, g_win);
    cudaGetSymbolAddress((void**)&psc, g_scores);
    cudaGetSymbolAddress((void**)&py,  g_y);
    cudaGetSymbolAddress((void**)&pgq, g_gq);
    cudaGetSymbolAddress((void**)&pgs, g_gs);
    cudaGetSymbolAddress((void**)&pgo, g_gout);
    cudaGetSymbolAddress((void**)&ppart, g_part);

    const float scl = 1.0f / sqrtf((float)AD);
    const size_t strBSA = (size_t)SS * AD;
    const size_t strBSS = (size_t)SS * SS;

    // Q, K, V projections: [16384,1024] x [1024,512] + bias
    gemm_tf32<false, 0><<<dim3(AD / TFBN, (BB * SS) / TFBM, 1), 256>>>(
        x, Wq, pq, DD, DD, AD, AD, 0, 0, 0, bq, nullptr, 0.f);
    gemm_tf32<false, 0><<<dim3(AD / TFBN, (BB * SS) / TFBM, 1), 256>>>(
        x, Wk, pk, DD, DD, AD, AD, 0, 0, 0, bk, nullptr, 0.f);
    gemm_tf32<false, 0><<<dim3(AD / TFBN, (BB * SS) / TFBM, 1), 256>>>(
        x, Wv, pv, DD, DD, AD, AD, 0, 0, 0, bv, nullptr, 0.f);

    // global query projection (two-stage)
    k_gq_part<<<dim3(AD / 128, 8, BB), 128>>>(gc, Wq, ppart);
    k_gq_red<<<dim3(AD / 128, BB), 128>>>(ppart, bq, pgq);

    // scores = q @ k^T / sqrt(A)   (per batch, NT)
    gemm_tf32<true, 1><<<dim3(SS / TFBN, SS / TFBM, BB), 256>>>(
        pq, pk, psc, AD, AD, AD, SS, strBSA, strBSA, strBSS, nullptr, nullptr, scl);

    // softmax over each of 16384 rows
    k_softmax<<<BB * SS, 256>>>(psc);

    // global scores + softmax
    k_gscores<<<(BB * SS) / 32, 256>>>(pk, pgq, pgs);
    k_softmax<<<BB, 256>>>(pgs);

    // global_out (two-stage)
    k_gout_part<<<dim3(AD / 128, 16, BB), 128>>>(pgs, pv, ppart);
    k_gout_red<<<dim3(AD / 128, BB), 128>>>(ppart, pgo);

    // win_out = 0.7 * weights@v + 0.3 * global_out   (per batch, NN)
    gemm_tf32<false, 2><<<dim3(AD / TFBN, SS / TFBM, BB), 256>>>(
        psc, pv, pwin, SS, SS, AD, AD, strBSS, strBSA, strBSA, pgo, nullptr, 0.f);

    // y = x + win_out @ Wo + bo
    gemm_tf32<false, 3><<<dim3(DD / TFBN, (BB * SS) / TFBM, 1), 256>>>(
        pwin, Wo, py, AD, AD, DD, DD, 0, 0, 0, bo, x, 0.f);

    // LayerNorm in place
    k_ln<<<BB * SS, 256>>>(py, gamma, beta);

    // avg_w -> d_out[8192:]   (two-stage column mean)
    k_colmean_part<<<dim3(SS / 256, 8, BB), 256>>>(psc, ppart);
    k_colmean_red<<<dim3(SS / 256, BB), 256>>>(ppart, pgs, outp + BB * DD);

    // context -> d_out[:8192]  (two-stage)
    k_context_part<<<dim3(DD / 256, 16, BB), 256>>>(outp + BB * DD, py, ppart);
    k_context_red<<<dim3(DD / 256, BB), 256>>>(ppart, outp);
}

// round 4
// speedup vs baseline: 3.3771x; 1.2335x over previous
#include <cuda_runtime.h>
#include <math.h>
#include <stdint.h>

// Problem constants
#define BB 8
#define SS 2048
#define DD 1024
#define AD 512

// Scratch (allocation-free rule: __device__ globals)
__device__ float g_q[BB * SS * AD];
__device__ float g_k[BB * SS * AD];
__device__ float g_v[BB * SS * AD];
__device__ float g_win[BB * SS * AD];
__device__ float g_scores[(size_t)BB * SS * SS];
__device__ float g_y[BB * SS * DD];
__device__ float g_gq[BB * AD];
__device__ float g_gs[BB * SS];
__device__ float g_gout[BB * AD];
__device__ float g_part[BB * 16 * SS];

// ---------------------------------------------------------------------------
// tf32 tensor-core GEMM v2.
// C[M,N] = A[M,K]*B[K,N] (TB=false) or A[M,K]*B[N,K]^T (TB=true)
// Block 128x128x32, 128 threads (4 warps as 2m x 2n, each warp 64x64).
// mma.sync.m16n8k8.tf32, cp.async double buffering, dynamic smem.
// EPI: 0 = +e0[n]; 1 = *scale; 2 = 0.7*acc + 0.3*e0[z*AD+n];
//      3 = +e0[n] + e1[m*ldc+n]
// ---------------------------------------------------------------------------
#define GBM 128
#define GBN 128
#define GBK 32
#define ASTR 36    // GBK+4 floats (144B, 16B-multiple; conflict-free frag loads)
#define BSTR 132   // GBN+4 floats (528B, 16B-multiple)

#define SMEM_NN ((2 * GBM * ASTR + 2 * GBK * BSTR) * 4)   // 70656 B
#define SMEM_NT ((2 * GBM * ASTR + 2 * GBM * ASTR) * 4)   // 73728 B

__device__ __forceinline__ void cp16(void* s, const void* g) {
    uint32_t sa = (uint32_t)__cvta_generic_to_shared(s);
    asm volatile("cp.async.cg.shared.global [%0], [%1], 16;\n" :: "r"(sa), "l"(g));
}
__device__ __forceinline__ uint32_t f2tf(float f) {
    uint32_t u;
    asm("cvt.rna.tf32.f32 %0, %1;" : "=r"(u) : "f"(f));
    return u;
}

template <bool TB, int EPI>
__global__ void __launch_bounds__(128, 2) gemm_tf32(
    const float* __restrict__ Am, const float* __restrict__ Bm, float* __restrict__ Cm,
    int K, int lda, int ldb, int ldc,
    size_t sA, size_t sB, size_t sC,
    const float* __restrict__ e0, const float* __restrict__ e1, float scale)
{
    extern __shared__ float sh[];
    float* As = sh;                         // 2 stages x 128 x ASTR
    float* Bs = sh + 2 * GBM * ASTR;        // NN: 2 x 32 x BSTR ; NT: 2 x 128 x ASTR

    const float* Ap = Am + (size_t)blockIdx.z * sA;
    const float* Bp = Bm + (size_t)blockIdx.z * sB;
    float* Cp = Cm + (size_t)blockIdx.z * sC;

    const int tid = threadIdx.x;
    const int wid = tid >> 5;
    const int lane = tid & 31;
    const int wm = wid >> 1;       // 0..1 -> 64 rows each
    const int wn = wid & 1;        // 0..1 -> 64 cols each
    const int g = lane >> 2;       // 0..7
    const int t = lane & 3;        // 0..3
    const int m0 = blockIdx.y * GBM;
    const int n0 = blockIdx.x * GBN;

    float acc[4][8][4];
#pragma unroll
    for (int i = 0; i < 4; i++)
#pragma unroll
        for (int j = 0; j < 8; j++)
#pragma unroll
            for (int c = 0; c < 4; c++) acc[i][j][c] = 0.f;

    auto copy_stage = [&](int st, int k0) {
        float* Ad = As + st * GBM * ASTR;
        // A tile: 128 rows x 8 quads = 1024 chunks, 8 per thread
#pragma unroll
        for (int i = 0; i < 8; i++) {
            int c = tid + 128 * i;
            int row = c >> 3, q = (c & 7) << 2;
            cp16(&Ad[row * ASTR + q], Ap + (size_t)(m0 + row) * lda + k0 + q);
        }
        if (TB) {
            float* Bd = Bs + st * GBM * ASTR;
#pragma unroll
            for (int i = 0; i < 8; i++) {
                int c = tid + 128 * i;
                int row = c >> 3, q = (c & 7) << 2;
                cp16(&Bd[row * ASTR + q], Bp + (size_t)(n0 + row) * ldb + k0 + q);
            }
        } else {
            float* Bd = Bs + st * GBK * BSTR;
#pragma unroll
            for (int i = 0; i < 8; i++) {
                int c = tid + 128 * i;
                int row = c >> 5, q = (c & 31) << 2;
                cp16(&Bd[row * BSTR + q], Bp + (size_t)(k0 + row) * ldb + n0 + q);
            }
        }
    };

    copy_stage(0, 0);
    asm volatile("cp.async.commit_group;\n");
    asm volatile("cp.async.wait_group 0;\n");
    __syncthreads();

    const int nk = K / GBK;
    for (int kt = 0; kt < nk; kt++) {
        int cur = kt & 1, nxt = cur ^ 1;
        if (kt + 1 < nk) {
            copy_stage(nxt, (kt + 1) * GBK);
            asm volatile("cp.async.commit_group;\n");
        }
        const float* Ac = As + cur * GBM * ASTR;
        const float* Bc = TB ? (Bs + cur * GBM * ASTR) : (Bs + cur * GBK * BSTR);
#pragma unroll
        for (int ks = 0; ks < 4; ks++) {
            const int kb = ks * 8;
            uint32_t afr[4][4];
#pragma unroll
            for (int mt = 0; mt < 4; mt++) {
                int r = wm * 64 + mt * 16 + g;
                afr[mt][0] = f2tf(Ac[(r)     * ASTR + kb + t]);
                afr[mt][1] = f2tf(Ac[(r + 8) * ASTR + kb + t]);
                afr[mt][2] = f2tf(Ac[(r)     * ASTR + kb + t + 4]);
                afr[mt][3] = f2tf(Ac[(r + 8) * ASTR + kb + t + 4]);
            }
#pragma unroll
            for (int nt = 0; nt < 8; nt++) {
                int n = wn * 64 + nt * 8 + g;
                uint32_t b0, b1;
                if (TB) {
                    b0 = f2tf(Bc[n * ASTR + kb + t]);
                    b1 = f2tf(Bc[n * ASTR + kb + t + 4]);
                } else {
                    b0 = f2tf(Bc[(kb + t) * BSTR + n]);
                    b1 = f2tf(Bc[(kb + t + 4) * BSTR + n]);
                }
#pragma unroll
                for (int mt = 0; mt < 4; mt++) {
                    asm volatile(
                        "mma.sync.aligned.m16n8k8.row.col.f32.tf32.tf32.f32 "
                        "{%0,%1,%2,%3}, {%4,%5,%6,%7}, {%8,%9}, {%0,%1,%2,%3};\n"
                        : "+f"(acc[mt][nt][0]), "+f"(acc[mt][nt][1]),
                          "+f"(acc[mt][nt][2]), "+f"(acc[mt][nt][3])
                        : "r"(afr[mt][0]), "r"(afr[mt][1]), "r"(afr[mt][2]), "r"(afr[mt][3]),
                          "r"(b0), "r"(b1));
                }
            }
        }
        if (kt + 1 < nk) asm volatile("cp.async.wait_group 0;\n");
        __syncthreads();
    }

    // Epilogue
#pragma unroll
    for (int mt = 0; mt < 4; mt++) {
#pragma unroll
        for (int nt = 0; nt < 8; nt++) {
            int row = m0 + wm * 64 + mt * 16 + g;
            int col = n0 + wn * 64 + nt * 8 + t * 2;
#pragma unroll
            for (int h = 0; h < 2; h++) {
                int r = row + h * 8;
                float v0 = acc[mt][nt][h * 2 + 0];
                float v1 = acc[mt][nt][h * 2 + 1];
                if (EPI == 0) { v0 += e0[col]; v1 += e0[col + 1]; }
                else if (EPI == 1) { v0 *= scale; v1 *= scale; }
                else if (EPI == 2) {
                    v0 = 0.7f * v0 + 0.3f * e0[blockIdx.z * AD + col];
                    v1 = 0.7f * v1 + 0.3f * e0[blockIdx.z * AD + col + 1];
                } else if (EPI == 3) {
                    v0 += e0[col]     + e1[(size_t)r * ldc + col];
                    v1 += e0[col + 1] + e1[(size_t)r * ldc + col + 1];
                }
                *(float2*)&Cp[(size_t)r * ldc + col] = make_float2(v0, v1);
            }
        }
    }
}

// ---------------------------------------------------------------------------
// gq two-stage
// ---------------------------------------------------------------------------
__global__ void __launch_bounds__(128) k_gq_part(
    const float* __restrict__ gc, const float* __restrict__ W, float* __restrict__ part)
{
    int a = blockIdx.x * 128 + threadIdx.x;
    int dc = blockIdx.y, b = blockIdx.z;
    const float* gv = gc + (size_t)b * DD + dc * 128;
    const float* Wp = W + (size_t)(dc * 128) * AD + a;
    float s = 0.f;
#pragma unroll 4
    for (int d = 0; d < 128; d++) s += gv[d] * Wp[(size_t)d * AD];
    part[((size_t)b * 8 + dc) * AD + a] = s;
}
__global__ void __launch_bounds__(128) k_gq_red(
    const float* __restrict__ part, const float* __restrict__ bias, float* __restrict__ gq)
{
    int a = blockIdx.x * 128 + threadIdx.x;
    int b = blockIdx.y;
    float s = bias[a];
#pragma unroll
    for (int j = 0; j < 8; j++) s += part[((size_t)b * 8 + j) * AD + a];
    gq[b * AD + a] = s;
}

// ---------------------------------------------------------------------------
// gscores[b,s] = dot(gq[b,:], k[b,s,:]) / sqrt(AD)
// ---------------------------------------------------------------------------
__global__ void __launch_bounds__(256) k_gscores(
    const float* __restrict__ kp, const float* __restrict__ gq, float* __restrict__ gs)
{
    int t = threadIdx.x;
    int key = blockIdx.x * 32 + (t >> 3);
    int lane = t & 7;
    int b = key / SS;
    int s = key % SS;
    const float* krow = kp + (size_t)key * AD;
    const float* q = gq + b * AD;
    float sum = 0.f;
    for (int a = lane; a < AD; a += 8) sum += krow[a] * q[a];
#pragma unroll
    for (int o = 4; o > 0; o >>= 1) sum += __shfl_down_sync(0xffffffffu, sum, o, 8);
    if (lane == 0) gs[b * SS + s] = sum * rsqrtf((float)AD);
}

// ---------------------------------------------------------------------------
// Register-resident row softmax (row len SS = 2048, 256 thr, 8 elems/thread)
// One global read + one global write.
// ---------------------------------------------------------------------------
__global__ void __launch_bounds__(256) k_softmax(float* __restrict__ data)
{
    float4* row = (float4*)(data + (size_t)blockIdx.x * SS);
    int t = threadIdx.x;
    float4 v0 = row[t];
    float4 v1 = row[t + 256];
    __shared__ float red[8];

    float m = fmaxf(fmaxf(fmaxf(v0.x, v0.y), fmaxf(v0.z, v0.w)),
                    fmaxf(fmaxf(v1.x, v1.y), fmaxf(v1.z, v1.w)));
#pragma unroll
    for (int o = 16; o > 0; o >>= 1) m = fmaxf(m, __shfl_xor_sync(0xffffffffu, m, o));
    if ((t & 31) == 0) red[t >> 5] = m;
    __syncthreads();
    m = red[0];
#pragma unroll
    for (int w = 1; w < 8; w++) m = fmaxf(m, red[w]);
    __syncthreads();

    v0.x = __expf(v0.x - m); v0.y = __expf(v0.y - m);
    v0.z = __expf(v0.z - m); v0.w = __expf(v0.w - m);
    v1.x = __expf(v1.x - m); v1.y = __expf(v1.y - m);
    v1.z = __expf(v1.z - m); v1.w = __expf(v1.w - m);

    float s = (v0.x + v0.y + v0.z + v0.w) + (v1.x + v1.y + v1.z + v1.w);
#pragma unroll
    for (int o = 16; o > 0; o >>= 1) s += __shfl_xor_sync(0xffffffffu, s, o);
    if ((t & 31) == 0) red[t >> 5] = s;
    __syncthreads();
    float tot = 0.f;
#pragma unroll
    for (int w = 0; w < 8; w++) tot += red[w];
    float inv = 1.f / tot;

    v0.x *= inv; v0.y *= inv; v0.z *= inv; v0.w *= inv;
    v1.x *= inv; v1.y *= inv; v1.z *= inv; v1.w *= inv;
    row[t] = v0;
    row[t + 256] = v1;
}

// ---------------------------------------------------------------------------
// global_out two-stage
// ---------------------------------------------------------------------------
__global__ void __launch_bounds__(128) k_gout_part(
    const float* __restrict__ gw, const float* __restrict__ vp, float* __restrict__ part)
{
    int a = blockIdx.x * 128 + threadIdx.x;
    int sc = blockIdx.y, b = blockIdx.z;
    const float* vb = vp + (size_t)b * SS * AD + (size_t)(sc * 128) * AD + a;
    const float* w = gw + b * SS + sc * 128;
    float sum = 0.f;
#pragma unroll 4
    for (int s = 0; s < 128; s++) sum += w[s] * vb[(size_t)s * AD];
    part[((size_t)b * 16 + sc) * AD + a] = sum;
}
__global__ void __launch_bounds__(128) k_gout_red(
    const float* __restrict__ part, float* __restrict__ go)
{
    int a = blockIdx.x * 128 + threadIdx.x;
    int b = blockIdx.y;
    float s = 0.f;
#pragma unroll
    for (int j = 0; j < 16; j++) s += part[((size_t)b * 16 + j) * AD + a];
    go[b * AD + a] = s;
}

// ---------------------------------------------------------------------------
// LayerNorm in-place on rows (len DD)
// ---------------------------------------------------------------------------
__global__ void __launch_bounds__(256) k_ln(
    float* __restrict__ y, const float* __restrict__ gamma, const float* __restrict__ beta)
{
    float* row = y + (size_t)blockIdx.x * DD;
    int t = threadIdx.x;
    float v[4], sum = 0.f, sq = 0.f;
#pragma unroll
    for (int i = 0; i < 4; i++) {
        v[i] = row[t + 256 * i];
        sum += v[i];
        sq += v[i] * v[i];
    }
    __shared__ float r1[8], r2[8];
#pragma unroll
    for (int o = 16; o > 0; o >>= 1) {
        sum += __shfl_xor_sync(0xffffffffu, sum, o);
        sq += __shfl_xor_sync(0xffffffffu, sq, o);
    }
    if ((t & 31) == 0) { r1[t >> 5] = sum; r2[t >> 5] = sq; }
    __syncthreads();
    float ts = 0.f, tq = 0.f;
#pragma unroll
    for (int w = 0; w < 8; w++) { ts += r1[w]; tq += r2[w]; }
    float mu = ts * (1.f / DD);
    float var = tq * (1.f / DD) - mu * mu;
    float inv = rsqrtf(var + 1e-5f);
#pragma unroll
    for (int i = 0; i < 4; i++) {
        int c = t + 256 * i;
        row[c] = (v[i] - mu) * inv * gamma[c] + beta[c];
    }
}

// ---------------------------------------------------------------------------
// colmean two-stage
// ---------------------------------------------------------------------------
__global__ void __launch_bounds__(256) k_colmean_part(
    const float* __restrict__ wts, float* __restrict__ part)
{
    int s = blockIdx.x * 256 + threadIdx.x;
    int qc = blockIdx.y, b = blockIdx.z;
    const float* base = wts + (size_t)b * SS * SS + (size_t)(qc * 256) * SS + s;
    float sum = 0.f;
#pragma unroll 4
    for (int q = 0; q < 256; q++) sum += base[(size_t)q * SS];
    part[((size_t)b * 8 + qc) * SS + s] = sum;
}
__global__ void __launch_bounds__(256) k_colmean_red(
    const float* __restrict__ part, const float* __restrict__ gw, float* __restrict__ avg)
{
    int s = blockIdx.x * 256 + threadIdx.x;
    int b = blockIdx.y;
    float sum = 0.f;
#pragma unroll
    for (int j = 0; j < 8; j++) sum += part[((size_t)b * 8 + j) * SS + s];
    avg[b * SS + s] = 0.7f * (sum * (1.f / SS)) + 0.3f * gw[b * SS + s];
}

// ---------------------------------------------------------------------------
// context two-stage
// ---------------------------------------------------------------------------
__global__ void __launch_bounds__(256) k_context_part(
    const float* __restrict__ avg, const float* __restrict__ y, float* __restrict__ part)
{
    int d = blockIdx.x * 256 + threadIdx.x;
    int sc = blockIdx.y, b = blockIdx.z;
    const float* yb = y + (size_t)b * SS * DD + (size_t)(sc * 128) * DD + d;
    const float* w = avg + b * SS + sc * 128;
    float sum = 0.f;
#pragma unroll 4
    for (int s = 0; s < 128; s++) sum += w[s] * yb[(size_t)s * DD];
    part[((size_t)b * 16 + sc) * DD + d] = sum;
}
__global__ void __launch_bounds__(256) k_context_red(
    const float* __restrict__ part, float* __restrict__ ctx)
{
    int d = blockIdx.x * 256 + threadIdx.x;
    int b = blockIdx.y;
    float s = 0.f;
#pragma unroll
    for (int j = 0; j < 16; j++) s += part[((size_t)b * 16 + j) * DD + d];
    ctx[b * DD + d] = s;
}

// ---------------------------------------------------------------------------

extern "C" void kernel_launch(void* const* d_in, const int* in_sizes, int n_in,
                              void* d_out, int out_size)
{
    const float* x     = (const float*)d_in[0];
    const float* gc    = (const float*)d_in[1];
    const float* Wq    = (const float*)d_in[2];
    const float* bq    = (const float*)d_in[3];
    const float* Wk    = (const float*)d_in[4];
    const float* bk    = (const float*)d_in[5];
    const float* Wv    = (const float*)d_in[6];
    const float* bv    = (const float*)d_in[7];
    const float* Wo    = (const float*)d_in[8];
    const float* bo    = (const float*)d_in[9];
    const float* gamma = (const float*)d_in[10];
    const float* beta  = (const float*)d_in[11];
    float* outp = (float*)d_out;

    float *pq, *pk, *pv, *pwin, *psc, *py, *pgq, *pgs, *pgo, *ppart;
    cudaGetSymbolAddress((void**)&pq,  g_q);
    cudaGetSymbolAddress((void**)&pk,  g_k);
    cudaGetSymbolAddress((void**)&pv,  g_v);
    cudaGetSymbolAddress((void**)&pwin, g_win);
    cudaGetSymbolAddress((void**)&psc, g_scores);
    cudaGetSymbolAddress((void**)&py,  g_y);
    cudaGetSymbolAddress((void**)&pgq, g_gq);
    cudaGetSymbolAddress((void**)&pgs, g_gs);
    cudaGetSymbolAddress((void**)&pgo, g_gout);
    cudaGetSymbolAddress((void**)&ppart, g_part);

    // Opt-in to >48KB dynamic smem (idempotent host attr calls; no allocation)
    cudaFuncSetAttribute(gemm_tf32<false, 0>, cudaFuncAttributeMaxDynamicSharedMemorySize, SMEM_NN);
    cudaFuncSetAttribute(gemm_tf32<false, 2>, cudaFuncAttributeMaxDynamicSharedMemorySize, SMEM_NN);
    cudaFuncSetAttribute(gemm_tf32<false, 3>, cudaFuncAttributeMaxDynamicSharedMemorySize, SMEM_NN);
    cudaFuncSetAttribute(gemm_tf32<true, 1>,  cudaFuncAttributeMaxDynamicSharedMemorySize, SMEM_NT);

    const float scl = 1.0f / sqrtf((float)AD);
    const size_t strBSA = (size_t)SS * AD;
    const size_t strBSS = (size_t)SS * SS;

    // Q, K, V projections: [16384,1024] x [1024,512] + bias
    gemm_tf32<false, 0><<<dim3(AD / GBN, (BB * SS) / GBM, 1), 128, SMEM_NN>>>(
        x, Wq, pq, DD, DD, AD, AD, 0, 0, 0, bq, nullptr, 0.f);
    gemm_tf32<false, 0><<<dim3(AD / GBN, (BB * SS) / GBM, 1), 128, SMEM_NN>>>(
        x, Wk, pk, DD, DD, AD, AD, 0, 0, 0, bk, nullptr, 0.f);
    gemm_tf32<false, 0><<<dim3(AD / GBN, (BB * SS) / GBM, 1), 128, SMEM_NN>>>(
        x, Wv, pv, DD, DD, AD, AD, 0, 0, 0, bv, nullptr, 0.f);

    // global query projection (two-stage)
    k_gq_part<<<dim3(AD / 128, 8, BB), 128>>>(gc, Wq, ppart);
    k_gq_red<<<dim3(AD / 128, BB), 128>>>(ppart, bq, pgq);

    // scores = q @ k^T / sqrt(A)   (per batch, NT)
    gemm_tf32<true, 1><<<dim3(SS / GBN, SS / GBM, BB), 128, SMEM_NT>>>(
        pq, pk, psc, AD, AD, AD, SS, strBSA, strBSA, strBSS, nullptr, nullptr, scl);

    // softmax over each of 16384 rows
    k_softmax<<<BB * SS, 256>>>(psc);

    // global scores + softmax
    k_gscores<<<(BB * SS) / 32, 256>>>(pk, pgq, pgs);
    k_softmax<<<BB, 256>>>(pgs);

    // global_out (two-stage)
    k_gout_part<<<dim3(AD / 128, 16, BB), 128>>>(pgs, pv, ppart);
    k_gout_red<<<dim3(AD / 128, BB), 128>>>(ppart, pgo);

    // win_out = 0.7 * weights@v + 0.3 * global_out   (per batch, NN)
    gemm_tf32<false, 2><<<dim3(AD / GBN, SS / GBM, BB), 128, SMEM_NN>>>(
        psc, pv, pwin, SS, SS, AD, AD, strBSS, strBSA, strBSA, pgo, nullptr, 0.f);

    // y = x + win_out @ Wo + bo
    gemm_tf32<false, 3><<<dim3(DD / GBN, (BB * SS) / GBM, 1), 128, SMEM_NN>>>(
        pwin, Wo, py, AD, AD, DD, DD, 0, 0, 0, bo, x, 0.f);

    // LayerNorm in place
    k_ln<<<BB * SS, 256>>>(py, gamma, beta);

    // avg_w -> d_out[8192:]   (two-stage column mean)
    k_colmean_part<<<dim3(SS / 256, 8, BB), 256>>>(psc, ppart);
    k_colmean_red<<<dim3(SS / 256, BB), 256>>>(ppart, pgs, outp + BB * DD);

    // context -> d_out[:8192]  (two-stage)
    k_context_part<<<dim3(DD / 256, 16, BB), 256>>>(outp + BB * DD, py, ppart);
    k_context_red<<<dim3(DD / 256, BB), 256>>>(ppart, outp);
}

// round 6
// speedup vs baseline: 4.9761x; 1.4735x over previous
#include <cuda_runtime.h>
#include <cuda_fp16.h>
#include <math.h>
#include <stdint.h>

// Problem constants
#define BB 8
#define SS 2048
#define DD 1024
#define AD 512

// ---------------------------------------------------------------------------
// Scratch (__device__ globals; allocation-free rule)
// ---------------------------------------------------------------------------
__device__ float  g_v[BB * SS * AD];                  // fp32 V (for global_out)
__device__ float  g_scores[(size_t)BB * SS * SS];     // fp32 softmax weights
__device__ float  g_y[BB * SS * DD];
__device__ float  g_gq[BB * AD];
__device__ float  g_gs[BB * SS];
__device__ float  g_gout[BB * AD];
__device__ float  g_part[BB * 16 * SS];

__device__ __half g_xh[BB * SS * DD];                 // half x
__device__ __half g_wqt[AD * DD];                     // Wq^T half [A][D]
__device__ __half g_wkt[AD * DD];
__device__ __half g_wvt[AD * DD];
__device__ __half g_wot[DD * AD];                     // Wo^T half [D][A]
__device__ __half g_qh[BB * SS * AD];
__device__ __half g_kh[BB * SS * AD];
__device__ __half g_vth[BB * SS * AD];                // V^T half [b][a][s]
__device__ __half g_wh[(size_t)BB * SS * SS];         // half softmax weights
__device__ __half g_winh[BB * SS * AD];

// ---------------------------------------------------------------------------
// fp16 tensor-core GEMM, all-NT: C[m][n] = sum_k A[m][k] * B[n][k]
// Block 128x128x32, 128 threads (4 warps 2x2, warp tile 64x64).
// mma.sync.m16n8k16.f16 with fp32 accum, cp.async double buffering.
// EPI: 0 half out +e0[n]; 1 f32 out +e0[n]; 2 f32 out *scale;
//      3 half out 0.7*acc+0.3*e0[z*AD+n]; 4 f32 out +e0[n]+e1[m*ldc+n]
// ---------------------------------------------------------------------------
#define HSTR 40   // row stride in halves (80 B)

__device__ __forceinline__ void cp16(void* s, const void* g) {
    uint32_t sa = (uint32_t)__cvta_generic_to_shared(s);
    asm volatile("cp.async.cg.shared.global [%0], [%1], 16;\n" :: "r"(sa), "l"(g));
}

template <int EPI>
__global__ void __launch_bounds__(128, 3) gemm_h(
    const __half* __restrict__ Am, const __half* __restrict__ Bm,
    float* __restrict__ Cf, __half* __restrict__ Ch,
    int K, int lda, int ldb, int ldc,
    size_t sA, size_t sB, size_t sC,
    const float* __restrict__ e0, const float* __restrict__ e1, float scale)
{
    __shared__ __half As[2][128][HSTR];
    __shared__ __half Bs[2][128][HSTR];

    const __half* Ap = Am + (size_t)blockIdx.z * sA;
    const __half* Bp = Bm + (size_t)blockIdx.z * sB;

    const int tid = threadIdx.x;
    const int wid = tid >> 5;
    const int lane = tid & 31;
    const int wm = wid >> 1;
    const int wn = wid & 1;
    const int g = lane >> 2;
    const int t = lane & 3;
    const int m0 = blockIdx.y * 128;
    const int n0 = blockIdx.x * 128;

    float acc[4][8][4];
#pragma unroll
    for (int i = 0; i < 4; i++)
#pragma unroll
        for (int j = 0; j < 8; j++)
#pragma unroll
            for (int c = 0; c < 4; c++) acc[i][j][c] = 0.f;

    auto copy_stage = [&](int st, int k0) {
        // Each operand tile: 128 rows x 32 halves = 128 x 4 16B-chunks
        // = 512 chunks; 128 threads -> 4 chunks per thread per operand.
#pragma unroll
        for (int i = 0; i < 4; i++) {
            int c = tid + 128 * i;
            int row = c >> 2, off = (c & 3) << 3;
            cp16(&As[st][row][off], Ap + (size_t)(m0 + row) * lda + k0 + off);
        }
#pragma unroll
        for (int i = 0; i < 4; i++) {
            int c = tid + 128 * i;
            int row = c >> 2, off = (c & 3) << 3;
            cp16(&Bs[st][row][off], Bp + (size_t)(n0 + row) * ldb + k0 + off);
        }
    };

    copy_stage(0, 0);
    asm volatile("cp.async.commit_group;\n");
    asm volatile("cp.async.wait_group 0;\n");
    __syncthreads();

    const int nk = K / 32;
    for (int kt = 0; kt < nk; kt++) {
        int cur = kt & 1, nxt = cur ^ 1;
        if (kt + 1 < nk) {
            copy_stage(nxt, (kt + 1) * 32);
            asm volatile("cp.async.commit_group;\n");
        }
#pragma unroll
        for (int ks = 0; ks < 2; ks++) {
            const int kb = ks * 16;
            uint32_t afr[4][4];
#pragma unroll
            for (int mt = 0; mt < 4; mt++) {
                int r = wm * 64 + mt * 16 + g;
                afr[mt][0] = *(const uint32_t*)&As[cur][r][kb + 2 * t];
                afr[mt][1] = *(const uint32_t*)&As[cur][r + 8][kb + 2 * t];
                afr[mt][2] = *(const uint32_t*)&As[cur][r][kb + 8 + 2 * t];
                afr[mt][3] = *(const uint32_t*)&As[cur][r + 8][kb + 8 + 2 * t];
            }
#pragma unroll
            for (int nt = 0; nt < 8; nt++) {
                int n = wn * 64 + nt * 8 + g;
                uint32_t b0 = *(const uint32_t*)&Bs[cur][n][kb + 2 * t];
                uint32_t b1 = *(const uint32_t*)&Bs[cur][n][kb + 8 + 2 * t];
#pragma unroll
                for (int mt = 0; mt < 4; mt++) {
                    asm volatile(
                        "mma.sync.aligned.m16n8k16.row.col.f32.f16.f16.f32 "
                        "{%0,%1,%2,%3}, {%4,%5,%6,%7}, {%8,%9}, {%0,%1,%2,%3};\n"
                        : "+f"(acc[mt][nt][0]), "+f"(acc[mt][nt][1]),
                          "+f"(acc[mt][nt][2]), "+f"(acc[mt][nt][3])
                        : "r"(afr[mt][0]), "r"(afr[mt][1]), "r"(afr[mt][2]), "r"(afr[mt][3]),
                          "r"(b0), "r"(b1));
                }
            }
        }
        if (kt + 1 < nk) asm volatile("cp.async.wait_group 0;\n");
        __syncthreads();
    }

    // Epilogue (C frag: c0,c1 = row g cols 2t,2t+1; c2,c3 = row g+8)
#pragma unroll
    for (int mt = 0; mt < 4; mt++) {
#pragma unroll
        for (int nt = 0; nt < 8; nt++) {
            int row = m0 + wm * 64 + mt * 16 + g;
            int col = n0 + wn * 64 + nt * 8 + 2 * t;
#pragma unroll
            for (int h = 0; h < 2; h++) {
                int r = row + h * 8;
                float v0 = acc[mt][nt][h * 2 + 0];
                float v1 = acc[mt][nt][h * 2 + 1];
                if (EPI == 0) {
                    v0 += e0[col]; v1 += e0[col + 1];
                    __half* Cp = Ch + (size_t)blockIdx.z * sC;
                    *(__half2*)&Cp[(size_t)r * ldc + col] = __floats2half2_rn(v0, v1);
                } else if (EPI == 1) {
                    v0 += e0[col]; v1 += e0[col + 1];
                    float* Cp = Cf + (size_t)blockIdx.z * sC;
                    *(float2*)&Cp[(size_t)r * ldc + col] = make_float2(v0, v1);
                } else if (EPI == 2) {
                    v0 *= scale; v1 *= scale;
                    float* Cp = Cf + (size_t)blockIdx.z * sC;
                    *(float2*)&Cp[(size_t)r * ldc + col] = make_float2(v0, v1);
                } else if (EPI == 3) {
                    v0 = 0.7f * v0 + 0.3f * e0[blockIdx.z * AD + col];
                    v1 = 0.7f * v1 + 0.3f * e0[blockIdx.z * AD + col + 1];
                    __half* Cp = Ch + (size_t)blockIdx.z * sC;
                    *(__half2*)&Cp[(size_t)r * ldc + col] = __floats2half2_rn(v0, v1);
                } else {
                    v0 += e0[col]     + e1[(size_t)r * ldc + col];
                    v1 += e0[col + 1] + e1[(size_t)r * ldc + col + 1];
                    float* Cp = Cf + (size_t)blockIdx.z * sC;
                    *(float2*)&Cp[(size_t)r * ldc + col] = make_float2(v0, v1);
                }
            }
        }
    }
}

// ---------------------------------------------------------------------------
// Elementwise f32 -> f16
// ---------------------------------------------------------------------------
__global__ void __launch_bounds__(256) k_conv_h(const float4* __restrict__ in,
                                               __half* __restrict__ out)
{
    int i = blockIdx.x * 256 + threadIdx.x;
    float4 v = in[i];
    __half2* o = (__half2*)(out + (size_t)i * 4);
    o[0] = __floats2half2_rn(v.x, v.y);
    o[1] = __floats2half2_rn(v.z, v.w);
}

// ---------------------------------------------------------------------------
// Transpose + convert: src f32 [R][C] -> dst half [C][R].  block (32,8)
// ---------------------------------------------------------------------------
__global__ void k_transpose_h(const float* __restrict__ src, __half* __restrict__ dst,
                              int R, int C, size_t sSrc, size_t sDst)
{
    __shared__ float t[32][33];
    src += (size_t)blockIdx.z * sSrc;
    dst += (size_t)blockIdx.z * sDst;
    int c0 = blockIdx.x * 32, r0 = blockIdx.y * 32;
    int tx = threadIdx.x, ty = threadIdx.y;
#pragma unroll
    for (int i = 0; i < 32; i += 8)
        t[ty + i][tx] = src[(size_t)(r0 + ty + i) * C + c0 + tx];
    __syncthreads();
#pragma unroll
    for (int i = 0; i < 32; i += 8)
        dst[(size_t)(c0 + ty + i) * R + r0 + tx] = __float2half(t[tx][ty + i]);
}

// ---------------------------------------------------------------------------
// gq two-stage (fp32 Wq)
// ---------------------------------------------------------------------------
__global__ void __launch_bounds__(128) k_gq_part(
    const float* __restrict__ gc, const float* __restrict__ W, float* __restrict__ part)
{
    int a = blockIdx.x * 128 + threadIdx.x;
    int dc = blockIdx.y, b = blockIdx.z;
    const float* gv = gc + (size_t)b * DD + dc * 128;
    const float* Wp = W + (size_t)(dc * 128) * AD + a;
    float s = 0.f;
#pragma unroll 4
    for (int d = 0; d < 128; d++) s += gv[d] * Wp[(size_t)d * AD];
    part[((size_t)b * 8 + dc) * AD + a] = s;
}
__global__ void __launch_bounds__(128) k_gq_red(
    const float* __restrict__ part, const float* __restrict__ bias, float* __restrict__ gq)
{
    int a = blockIdx.x * 128 + threadIdx.x;
    int b = blockIdx.y;
    float s = bias[a];
#pragma unroll
    for (int j = 0; j < 8; j++) s += part[((size_t)b * 8 + j) * AD + a];
    gq[b * AD + a] = s;
}

// ---------------------------------------------------------------------------
// gscores[b,s] = dot(gq[b,:], kh[b,s,:]) / sqrt(AD)   (half K)
// ---------------------------------------------------------------------------
__global__ void __launch_bounds__(256) k_gscores(
    const __half* __restrict__ kp, const float* __restrict__ gq, float* __restrict__ gs)
{
    int t = threadIdx.x;
    int key = blockIdx.x * 32 + (t >> 3);
    int lane = t & 7;
    int b = key / SS;
    int s = key % SS;
    const __half* krow = kp + (size_t)key * AD;
    const float* q = gq + b * AD;
    float sum = 0.f;
    for (int a = lane; a < AD; a += 8) sum += __half2float(krow[a]) * q[a];
#pragma unroll
    for (int o = 4; o > 0; o >>= 1) sum += __shfl_down_sync(0xffffffffu, sum, o, 8);
    if (lane == 0) gs[b * SS + s] = sum * rsqrtf((float)AD);
}

// ---------------------------------------------------------------------------
// Register-resident row softmax (SS cols); optionally dual-writes half copy.
// ---------------------------------------------------------------------------
__global__ void __launch_bounds__(256) k_softmax(float* __restrict__ data,
                                                 __half* __restrict__ hout)
{
    float4* row = (float4*)(data + (size_t)blockIdx.x * SS);
    int t = threadIdx.x;
    float4 v0 = row[t];
    float4 v1 = row[t + 256];
    __shared__ float red[8];

    float m = fmaxf(fmaxf(fmaxf(v0.x, v0.y), fmaxf(v0.z, v0.w)),
                    fmaxf(fmaxf(v1.x, v1.y), fmaxf(v1.z, v1.w)));
#pragma unroll
    for (int o = 16; o > 0; o >>= 1) m = fmaxf(m, __shfl_xor_sync(0xffffffffu, m, o));
    if ((t & 31) == 0) red[t >> 5] = m;
    __syncthreads();
    m = red[0];
#pragma unroll
    for (int w = 1; w < 8; w++) m = fmaxf(m, red[w]);
    __syncthreads();

    v0.x = __expf(v0.x - m); v0.y = __expf(v0.y - m);
    v0.z = __expf(v0.z - m); v0.w = __expf(v0.w - m);
    v1.x = __expf(v1.x - m); v1.y = __expf(v1.y - m);
    v1.z = __expf(v1.z - m); v1.w = __expf(v1.w - m);

    float s = (v0.x + v0.y + v0.z + v0.w) + (v1.x + v1.y + v1.z + v1.w);
#pragma unroll
    for (int o = 16; o > 0; o >>= 1) s += __shfl_xor_sync(0xffffffffu, s, o);
    if ((t & 31) == 0) red[t >> 5] = s;
    __syncthreads();
    float tot = 0.f;
#pragma unroll
    for (int w = 0; w < 8; w++) tot += red[w];
    float inv = 1.f / tot;

    v0.x *= inv; v0.y *= inv; v0.z *= inv; v0.w *= inv;
    v1.x *= inv; v1.y *= inv; v1.z *= inv; v1.w *= inv;
    row[t] = v0;
    row[t + 256] = v1;
    if (hout) {
        __half2* h = (__half2*)(hout + (size_t)blockIdx.x * SS);
        h[2 * t]           = __floats2half2_rn(v0.x, v0.y);
        h[2 * t + 1]       = __floats2half2_rn(v0.z, v0.w);
        h[2 * (t + 256)]     = __floats2half2_rn(v1.x, v1.y);
        h[2 * (t + 256) + 1] = __floats2half2_rn(v1.z, v1.w);
    }
}

// ---------------------------------------------------------------------------
// global_out two-stage (fp32 v)
// ---------------------------------------------------------------------------
__global__ void __launch_bounds__(128) k_gout_part(
    const float* __restrict__ gw, const float* __restrict__ vp, float* __restrict__ part)
{
    int a = blockIdx.x * 128 + threadIdx.x;
    int sc = blockIdx.y, b = blockIdx.z;
    const float* vb = vp + (size_t)b * SS * AD + (size_t)(sc * 128) * AD + a;
    const float* w = gw + b * SS + sc * 128;
    float sum = 0.f;
#pragma unroll 4
    for (int s = 0; s < 128; s++) sum += w[s] * vb[(size_t)s * AD];
    part[((size_t)b * 16 + sc) * AD + a] = sum;
}
__global__ void __launch_bounds__(128) k_gout_red(
    const float* __restrict__ part, float* __restrict__ go)
{
    int a = blockIdx.x * 128 + threadIdx.x;
    int b = blockIdx.y;
    float s = 0.f;
#pragma unroll
    for (int j = 0; j < 16; j++) s += part[((size_t)b * 16 + j) * AD + a];
    go[b * AD + a] = s;
}

// ---------------------------------------------------------------------------
// LayerNorm in-place (rows of DD)
// ---------------------------------------------------------------------------
__global__ void __launch_bounds__(256) k_ln(
    float* __restrict__ y, const float* __restrict__ gamma, const float* __restrict__ beta)
{
    float* row = y + (size_t)blockIdx.x * DD;
    int t = threadIdx.x;
    float v[4], sum = 0.f, sq = 0.f;
#pragma unroll
    for (int i = 0; i < 4; i++) {
        v[i] = row[t + 256 * i];
        sum += v[i];
        sq += v[i] * v[i];
    }
    __shared__ float r1[8], r2[8];
#pragma unroll
    for (int o = 16; o > 0; o >>= 1) {
        sum += __shfl_xor_sync(0xffffffffu, sum, o);
        sq += __shfl_xor_sync(0xffffffffu, sq, o);
    }
    if ((t & 31) == 0) { r1[t >> 5] = sum; r2[t >> 5] = sq; }
    __syncthreads();
    float ts = 0.f, tq = 0.f;
#pragma unroll
    for (int w = 0; w < 8; w++) { ts += r1[w]; tq += r2[w]; }
    float mu = ts * (1.f / DD);
    float var = tq * (1.f / DD) - mu * mu;
    float inv = rsqrtf(var + 1e-5f);
#pragma unroll
    for (int i = 0; i < 4; i++) {
        int c = t + 256 * i;
        row[c] = (v[i] - mu) * inv * gamma[c] + beta[c];
    }
}

// ---------------------------------------------------------------------------
// colmean two-stage (fp32 weights)
// ---------------------------------------------------------------------------
__global__ void __launch_bounds__(256) k_colmean_part(
    const float* __restrict__ wts, float* __restrict__ part)
{
    int s = blockIdx.x * 256 + threadIdx.x;
    int qc = blockIdx.y, b = blockIdx.z;
    const float* base = wts + (size_t)b * SS * SS + (size_t)(qc * 256) * SS + s;
    float sum = 0.f;
#pragma unroll 4
    for (int q = 0; q < 256; q++) sum += base[(size_t)q * SS];
    part[((size_t)b * 8 + qc) * SS + s] = sum;
}
__global__ void __launch_bounds__(256) k_colmean_red(
    const float* __restrict__ part, const float* __restrict__ gw, float* __restrict__ avg)
{
    int s = blockIdx.x * 256 + threadIdx.x;
    int b = blockIdx.y;
    float sum = 0.f;
#pragma unroll
    for (int j = 0; j < 8; j++) sum += part[((size_t)b * 8 + j) * SS + s];
    avg[b * SS + s] = 0.7f * (sum * (1.f / SS)) + 0.3f * gw[b * SS + s];
}

// ---------------------------------------------------------------------------
// context two-stage
// ---------------------------------------------------------------------------
__global__ void __launch_bounds__(256) k_context_part(
    const float* __restrict__ avg, const float* __restrict__ y, float* __restrict__ part)
{
    int d = blockIdx.x * 256 + threadIdx.x;
    int sc = blockIdx.y, b = blockIdx.z;
    const float* yb = y + (size_t)b * SS * DD + (size_t)(sc * 128) * DD + d;
    const float* w = avg + b * SS + sc * 128;
    float sum = 0.f;
#pragma unroll 4
    for (int s = 0; s < 128; s++) sum += w[s] * yb[(size_t)s * DD];
    part[((size_t)b * 16 + sc) * DD + d] = sum;
}
__global__ void __launch_bounds__(256) k_context_red(
    const float* __restrict__ part, float* __restrict__ ctx)
{
    int d = blockIdx.x * 256 + threadIdx.x;
    int b = blockIdx.y;
    float s = 0.f;
#pragma unroll
    for (int j = 0; j < 16; j++) s += part[((size_t)b * 16 + j) * DD + d];
    ctx[b * DD + d] = s;
}

// ---------------------------------------------------------------------------

extern "C" void kernel_launch(void* const* d_in, const int* in_sizes, int n_in,
                              void* d_out, int out_size)
{
    const float* x     = (const float*)d_in[0];
    const float* gc    = (const float*)d_in[1];
    const float* Wq    = (const float*)d_in[2];
    const float* bq    = (const float*)d_in[3];
    const float* Wk    = (const float*)d_in[4];
    const float* bk    = (const float*)d_in[5];
    const float* Wv    = (const float*)d_in[6];
    const float* bv    = (const float*)d_in[7];
    const float* Wo    = (const float*)d_in[8];
    const float* bo    = (const float*)d_in[9];
    const float* gamma = (const float*)d_in[10];
    const float* beta  = (const float*)d_in[11];
    float* outp = (float*)d_out;

    float *pv, *psc, *py, *pgq, *pgs, *pgo, *ppart;
    __half *pxh, *pwqt, *pwkt, *pwvt, *pwot, *pqh, *pkh, *pvth, *pwh, *pwinh;
    cudaGetSymbolAddress((void**)&pv,   g_v);
    cudaGetSymbolAddress((void**)&psc,  g_scores);
    cudaGetSymbolAddress((void**)&py,   g_y);
    cudaGetSymbolAddress((void**)&pgq,  g_gq);
    cudaGetSymbolAddress((void**)&pgs,  g_gs);
    cudaGetSymbolAddress((void**)&pgo,  g_gout);
    cudaGetSymbolAddress((void**)&ppart, g_part);
    cudaGetSymbolAddress((void**)&pxh,  g_xh);
    cudaGetSymbolAddress((void**)&pwqt, g_wqt);
    cudaGetSymbolAddress((void**)&pwkt, g_wkt);
    cudaGetSymbolAddress((void**)&pwvt, g_wvt);
    cudaGetSymbolAddress((void**)&pwot, g_wot);
    cudaGetSymbolAddress((void**)&pqh,  g_qh);
    cudaGetSymbolAddress((void**)&pkh,  g_kh);
    cudaGetSymbolAddress((void**)&pvth, g_vth);
    cudaGetSymbolAddress((void**)&pwh,  g_wh);
    cudaGetSymbolAddress((void**)&pwinh, g_winh);

    const float scl = 1.0f / sqrtf((float)AD);
    const size_t strBSA = (size_t)SS * AD;
    const size_t strBSS = (size_t)SS * SS;

    // 1. x -> half
    k_conv_h<<<(BB * SS * DD) / 1024, 256>>>((const float4*)x, pxh);
    // 2-5. weight transposes (half): W[D][A] -> Wt[A][D]; Wo[A][D] -> Wot[D][A]
    k_transpose_h<<<dim3(AD / 32, DD / 32, 1), dim3(32, 8)>>>(Wq, pwqt, DD, AD, 0, 0);
    k_transpose_h<<<dim3(AD / 32, DD / 32, 1), dim3(32, 8)>>>(Wk, pwkt, DD, AD, 0, 0);
    k_transpose_h<<<dim3(AD / 32, DD / 32, 1), dim3(32, 8)>>>(Wv, pwvt, DD, AD, 0, 0);
    k_transpose_h<<<dim3(DD / 32, AD / 32, 1), dim3(32, 8)>>>(Wo, pwot, AD, DD, 0, 0);

    // 6-8. Q,K,V projections (NT vs transposed weights): [16384,1024]x[512,1024]^T
    gemm_h<0><<<dim3(AD / 128, (BB * SS) / 128, 1), 128>>>(
        pxh, pwqt, nullptr, pqh, DD, DD, DD, AD, 0, 0, 0, bq, nullptr, 0.f);
    gemm_h<0><<<dim3(AD / 128, (BB * SS) / 128, 1), 128>>>(
        pxh, pwkt, nullptr, pkh, DD, DD, DD, AD, 0, 0, 0, bk, nullptr, 0.f);
    gemm_h<1><<<dim3(AD / 128, (BB * SS) / 128, 1), 128>>>(
        pxh, pwvt, pv, nullptr, DD, DD, DD, AD, 0, 0, 0, bv, nullptr, 0.f);

    // 9. v fp32 [s][a] -> vT half [a][s] per batch
    k_transpose_h<<<dim3(AD / 32, SS / 32, BB), dim3(32, 8)>>>(
        pv, pvth, SS, AD, strBSA, strBSA);

    // 10-11. global query projection (fp32)
    k_gq_part<<<dim3(AD / 128, 8, BB), 128>>>(gc, Wq, ppart);
    k_gq_red<<<dim3(AD / 128, BB), 128>>>(ppart, bq, pgq);

    // 12. scores = q @ k^T / sqrt(A)  (NT, half)
    gemm_h<2><<<dim3(SS / 128, SS / 128, BB), 128>>>(
        pqh, pkh, psc, nullptr, AD, AD, AD, SS, strBSA, strBSA, strBSS,
        nullptr, nullptr, scl);

    // 13. softmax (fp32 in place + half copy)
    k_softmax<<<BB * SS, 256>>>(psc, pwh);

    // 14-15. global scores + softmax (fp32 only)
    k_gscores<<<(BB * SS) / 32, 256>>>(pkh, pgq, pgs);
    k_softmax<<<BB, 256>>>(pgs, nullptr);

    // 16-17. global_out (fp32 v)
    k_gout_part<<<dim3(AD / 128, 16, BB), 128>>>(pgs, pv, ppart);
    k_gout_red<<<dim3(AD / 128, BB), 128>>>(ppart, pgo);

    // 18. win = 0.7*weights@v + 0.3*gout  (NT: A=wh [q][s], B=vT [a][s])
    gemm_h<3><<<dim3(AD / 128, SS / 128, BB), 128>>>(
        pwh, pvth, nullptr, pwinh, SS, SS, SS, AD, strBSS, strBSA, strBSA,
        pgo, nullptr, 0.f);

    // 19. y = x + win @ Wo + bo  (NT: B=WoT [d][a])
    gemm_h<4><<<dim3(DD / 128, (BB * SS) / 128, 1), 128>>>(
        pwinh, pwot, py, nullptr, AD, AD, AD, DD, 0, 0, 0, bo, x, 0.f);

    // 20. LayerNorm
    k_ln<<<BB * SS, 256>>>(py, gamma, beta);

    // 21-22. avg_w (fp32 weights)
    k_colmean_part<<<dim3(SS / 256, 8, BB), 256>>>(psc, ppart);
    k_colmean_red<<<dim3(SS / 256, BB), 256>>>(ppart, pgs, outp + BB * DD);

    // 23-24. context
    k_context_part<<<dim3(DD / 256, 16, BB), 256>>>(outp + BB * DD, py, ppart);
    k_context_red<<<dim3(DD / 256, BB), 256>>>(ppart, outp);
}

// round 7
// speedup vs baseline: 5.2959x; 1.0643x over previous
#include <cuda_runtime.h>
#include <cuda_fp16.h>
#include <math.h>
#include <stdint.h>

// Problem constants
#define BB 8
#define SS 2048
#define DD 1024
#define AD 512

// ---------------------------------------------------------------------------
// Scratch (__device__ globals; allocation-free rule)
// ---------------------------------------------------------------------------
__device__ float  g_v[BB * SS * AD];                  // fp32 V (for global_out)
__device__ float  g_scores[(size_t)BB * SS * SS];     // fp32 raw scores
__device__ float  g_y[BB * SS * DD];
__device__ float  g_gq[BB * AD];
__device__ float  g_gs[BB * SS];
__device__ float  g_gout[BB * AD];
__device__ float  g_part[BB * 16 * SS];

__device__ __half g_xh[BB * SS * DD];                 // half x
__device__ __half g_wqt[AD * DD];                     // Wq^T half [A][D]
__device__ __half g_wkt[AD * DD];
__device__ __half g_wvt[AD * DD];
__device__ __half g_wot[DD * AD];                     // Wo^T half [D][A]
__device__ __half g_qh[BB * SS * AD];
__device__ __half g_kh[BB * SS * AD];
__device__ __half g_vth[BB * SS * AD];                // V^T half [b][a][s]
__device__ __half g_wh[(size_t)BB * SS * SS];         // half softmax weights
__device__ __half g_winh[BB * SS * AD];

// ---------------------------------------------------------------------------
// fp16 tensor-core GEMM, all-NT: C[m][n] = sum_k A[m][k] * B[n][k]
// Block 128x128x32, 128 threads (4 warps 2x2, warp tile 64x64).
// mma.sync.m16n8k16 fp32-accum, ldmatrix fragment loads, cp.async 2-stage.
// EPI: 0 half out +e0[n]; 1 f32 out +e0[n]; 2 f32 out *scale;
//      3 half out 0.7*acc+0.3*e0[z*AD+n]; 4 f32 out +e0[n]+e1[m*ldc+n]
// ---------------------------------------------------------------------------
#define HSTR 40   // row stride in halves (80 B): LDSM phases conflict-free

__device__ __forceinline__ void cp16(void* s, const void* g) {
    uint32_t sa = (uint32_t)__cvta_generic_to_shared(s);
    asm volatile("cp.async.cg.shared.global [%0], [%1], 16;\n" :: "r"(sa), "l"(g));
}
#define LDSM4(r0, r1, r2, r3, a) \
    asm volatile("ldmatrix.sync.aligned.m8n8.x4.shared.b16 {%0,%1,%2,%3}, [%4];" \
                 : "=r"(r0), "=r"(r1), "=r"(r2), "=r"(r3) : "r"(a))

template <int EPI>
__global__ void __launch_bounds__(128, 3) gemm_h(
    const __half* __restrict__ Am, const __half* __restrict__ Bm,
    float* __restrict__ Cf, __half* __restrict__ Ch,
    int K, int lda, int ldb, int ldc,
    size_t sA, size_t sB, size_t sC,
    const float* __restrict__ e0, const float* __restrict__ e1, float scale)
{
    __shared__ __half As[2][128][HSTR];
    __shared__ __half Bs[2][128][HSTR];

    const __half* Ap = Am + (size_t)blockIdx.z * sA;
    const __half* Bp = Bm + (size_t)blockIdx.z * sB;

    const int tid = threadIdx.x;
    const int wid = tid >> 5;
    const int lane = tid & 31;
    const int wm = wid >> 1;
    const int wn = wid & 1;
    const int g = lane >> 2;
    const int t = lane & 3;
    const int m0 = blockIdx.y * 128;
    const int n0 = blockIdx.x * 128;

    // ldmatrix lane addressing: row = base + (lane&15), col = kb + (lane>>4)*8
    const int lrow = lane & 15;
    const int lcol = (lane >> 4) << 3;
    const uint32_t sAb = (uint32_t)__cvta_generic_to_shared(&As[0][0][0]);
    const uint32_t sBb = (uint32_t)__cvta_generic_to_shared(&Bs[0][0][0]);
    const uint32_t stageBytes = 128 * HSTR * 2;

    float acc[4][8][4];
#pragma unroll
    for (int i = 0; i < 4; i++)
#pragma unroll
        for (int j = 0; j < 8; j++)
#pragma unroll
            for (int c = 0; c < 4; c++) acc[i][j][c] = 0.f;

    auto copy_stage = [&](int st, int k0) {
        // 128 rows x 4 16B-chunks per operand = 512 chunks; 4/thread/operand
#pragma unroll
        for (int i = 0; i < 4; i++) {
            int c = tid + 128 * i;
            int row = c >> 2, off = (c & 3) << 3;
            cp16(&As[st][row][off], Ap + (size_t)(m0 + row) * lda + k0 + off);
        }
#pragma unroll
        for (int i = 0; i < 4; i++) {
            int c = tid + 128 * i;
            int row = c >> 2, off = (c & 3) << 3;
            cp16(&Bs[st][row][off], Bp + (size_t)(n0 + row) * ldb + k0 + off);
        }
    };

    copy_stage(0, 0);
    asm volatile("cp.async.commit_group;\n");
    asm volatile("cp.async.wait_group 0;\n");
    __syncthreads();

    const int nk = K / 32;
    for (int kt = 0; kt < nk; kt++) {
        int cur = kt & 1, nxt = cur ^ 1;
        if (kt + 1 < nk) {
            copy_stage(nxt, (kt + 1) * 32);
            asm volatile("cp.async.commit_group;\n");
        }
        uint32_t aBase = sAb + cur * stageBytes
                       + ((wm * 64 + lrow) * HSTR + lcol) * 2;
        uint32_t bBase = sBb + cur * stageBytes
                       + ((wn * 64 + lrow) * HSTR + lcol) * 2;
#pragma unroll
        for (int ks = 0; ks < 2; ks++) {
            const int kb = ks * 16;
            uint32_t afr[4][4];
#pragma unroll
            for (int mt = 0; mt < 4; mt++)
                LDSM4(afr[mt][0], afr[mt][1], afr[mt][2], afr[mt][3],
                      aBase + (mt * 16 * HSTR + kb) * 2);
#pragma unroll
            for (int p = 0; p < 4; p++) {
                // pair of n-tiles: regs {b0(nt), b0(nt+1), b1(nt), b1(nt+1)}
                uint32_t b00, b01, b10, b11;
                LDSM4(b00, b01, b10, b11, bBase + (p * 16 * HSTR + kb) * 2);
#pragma unroll
                for (int h = 0; h < 2; h++) {
                    int nt = p * 2 + h;
                    uint32_t b0 = h ? b01 : b00;
                    uint32_t b1 = h ? b11 : b10;
#pragma unroll
                    for (int mt = 0; mt < 4; mt++) {
                        asm volatile(
                            "mma.sync.aligned.m16n8k16.row.col.f32.f16.f16.f32 "
                            "{%0,%1,%2,%3}, {%4,%5,%6,%7}, {%8,%9}, {%0,%1,%2,%3};\n"
                            : "+f"(acc[mt][nt][0]), "+f"(acc[mt][nt][1]),
                              "+f"(acc[mt][nt][2]), "+f"(acc[mt][nt][3])
                            : "r"(afr[mt][0]), "r"(afr[mt][1]),
                              "r"(afr[mt][2]), "r"(afr[mt][3]),
                              "r"(b0), "r"(b1));
                    }
                }
            }
        }
        if (kt + 1 < nk) asm volatile("cp.async.wait_group 0;\n");
        __syncthreads();
    }

    // Epilogue (C frag: c0,c1 = row g cols 2t,2t+1; c2,c3 = row g+8)
#pragma unroll
    for (int mt = 0; mt < 4; mt++) {
#pragma unroll
        for (int nt = 0; nt < 8; nt++) {
            int row = m0 + wm * 64 + mt * 16 + g;
            int col = n0 + wn * 64 + nt * 8 + 2 * t;
#pragma unroll
            for (int h = 0; h < 2; h++) {
                int r = row + h * 8;
                float v0 = acc[mt][nt][h * 2 + 0];
                float v1 = acc[mt][nt][h * 2 + 1];
                if (EPI == 0) {
                    v0 += e0[col]; v1 += e0[col + 1];
                    __half* Cp = Ch + (size_t)blockIdx.z * sC;
                    *(__half2*)&Cp[(size_t)r * ldc + col] = __floats2half2_rn(v0, v1);
                } else if (EPI == 1) {
                    v0 += e0[col]; v1 += e0[col + 1];
                    float* Cp = Cf + (size_t)blockIdx.z * sC;
                    *(float2*)&Cp[(size_t)r * ldc + col] = make_float2(v0, v1);
                } else if (EPI == 2) {
                    v0 *= scale; v1 *= scale;
                    float* Cp = Cf + (size_t)blockIdx.z * sC;
                    *(float2*)&Cp[(size_t)r * ldc + col] = make_float2(v0, v1);
                } else if (EPI == 3) {
                    v0 = 0.7f * v0 + 0.3f * e0[blockIdx.z * AD + col];
                    v1 = 0.7f * v1 + 0.3f * e0[blockIdx.z * AD + col + 1];
                    __half* Cp = Ch + (size_t)blockIdx.z * sC;
                    *(__half2*)&Cp[(size_t)r * ldc + col] = __floats2half2_rn(v0, v1);
                } else {
                    v0 += e0[col]     + e1[(size_t)r * ldc + col];
                    v1 += e0[col + 1] + e1[(size_t)r * ldc + col + 1];
                    float* Cp = Cf + (size_t)blockIdx.z * sC;
                    *(float2*)&Cp[(size_t)r * ldc + col] = make_float2(v0, v1);
                }
            }
        }
    }
}

// ---------------------------------------------------------------------------
// Elementwise f32 -> f16
// ---------------------------------------------------------------------------
__global__ void __launch_bounds__(256) k_conv_h(const float4* __restrict__ in,
                                               __half* __restrict__ out)
{
    int i = blockIdx.x * 256 + threadIdx.x;
    float4 v = in[i];
    __half2* o = (__half2*)(out + (size_t)i * 4);
    o[0] = __floats2half2_rn(v.x, v.y);
    o[1] = __floats2half2_rn(v.z, v.w);
}

// ---------------------------------------------------------------------------
// Transpose + convert: src f32 [R][C] -> dst half [C][R].  block (32,8)
// ---------------------------------------------------------------------------
__global__ void k_transpose_h(const float* __restrict__ src, __half* __restrict__ dst,
                              int R, int C, size_t sSrc, size_t sDst)
{
    __shared__ float t[32][33];
    src += (size_t)blockIdx.z * sSrc;
    dst += (size_t)blockIdx.z * sDst;
    int c0 = blockIdx.x * 32, r0 = blockIdx.y * 32;
    int tx = threadIdx.x, ty = threadIdx.y;
#pragma unroll
    for (int i = 0; i < 32; i += 8)
        t[ty + i][tx] = src[(size_t)(r0 + ty + i) * C + c0 + tx];
    __syncthreads();
#pragma unroll
    for (int i = 0; i < 32; i += 8)
        dst[(size_t)(c0 + ty + i) * R + r0 + tx] = __float2half(t[tx][ty + i]);
}

// ---------------------------------------------------------------------------
// gq two-stage (fp32 Wq)
// ---------------------------------------------------------------------------
__global__ void __launch_bounds__(128) k_gq_part(
    const float* __restrict__ gc, const float* __restrict__ W, float* __restrict__ part)
{
    int a = blockIdx.x * 128 + threadIdx.x;
    int dc = blockIdx.y, b = blockIdx.z;
    const float* gv = gc + (size_t)b * DD + dc * 128;
    const float* Wp = W + (size_t)(dc * 128) * AD + a;
    float s = 0.f;
#pragma unroll 4
    for (int d = 0; d < 128; d++) s += gv[d] * Wp[(size_t)d * AD];
    part[((size_t)b * 8 + dc) * AD + a] = s;
}
__global__ void __launch_bounds__(128) k_gq_red(
    const float* __restrict__ part, const float* __restrict__ bias, float* __restrict__ gq)
{
    int a = blockIdx.x * 128 + threadIdx.x;
    int b = blockIdx.y;
    float s = bias[a];
#pragma unroll
    for (int j = 0; j < 8; j++) s += part[((size_t)b * 8 + j) * AD + a];
    gq[b * AD + a] = s;
}

// ---------------------------------------------------------------------------
// gscores[b,s] = dot(gq[b,:], kh[b,s,:]) / sqrt(AD)
// ---------------------------------------------------------------------------
__global__ void __launch_bounds__(256) k_gscores(
    const __half* __restrict__ kp, const float* __restrict__ gq, float* __restrict__ gs)
{
    int t = threadIdx.x;
    int key = blockIdx.x * 32 + (t >> 3);
    int lane = t & 7;
    int b = key / SS;
    int s = key % SS;
    const __half* krow = kp + (size_t)key * AD;
    const float* q = gq + b * AD;
    float sum = 0.f;
    for (int a = lane; a < AD; a += 8) sum += __half2float(krow[a]) * q[a];
#pragma unroll
    for (int o = 4; o > 0; o >>= 1) sum += __shfl_down_sync(0xffffffffu, sum, o, 8);
    if (lane == 0) gs[b * SS + s] = sum * rsqrtf((float)AD);
}

// ---------------------------------------------------------------------------
// Register-resident row softmax (SS cols).
// If hout != null: write ONLY the half copy (fp32 buffer left as raw scores).
// Else: write fp32 in place.
// ---------------------------------------------------------------------------
__global__ void __launch_bounds__(256) k_softmax(float* __restrict__ data,
                                                 __half* __restrict__ hout)
{
    float4* row = (float4*)(data + (size_t)blockIdx.x * SS);
    int t = threadIdx.x;
    float4 v0 = row[t];
    float4 v1 = row[t + 256];
    __shared__ float red[8];

    float m = fmaxf(fmaxf(fmaxf(v0.x, v0.y), fmaxf(v0.z, v0.w)),
                    fmaxf(fmaxf(v1.x, v1.y), fmaxf(v1.z, v1.w)));
#pragma unroll
    for (int o = 16; o > 0; o >>= 1) m = fmaxf(m, __shfl_xor_sync(0xffffffffu, m, o));
    if ((t & 31) == 0) red[t >> 5] = m;
    __syncthreads();
    m = red[0];
#pragma unroll
    for (int w = 1; w < 8; w++) m = fmaxf(m, red[w]);
    __syncthreads();

    v0.x = __expf(v0.x - m); v0.y = __expf(v0.y - m);
    v0.z = __expf(v0.z - m); v0.w = __expf(v0.w - m);
    v1.x = __expf(v1.x - m); v1.y = __expf(v1.y - m);
    v1.z = __expf(v1.z - m); v1.w = __expf(v1.w - m);

    float s = (v0.x + v0.y + v0.z + v0.w) + (v1.x + v1.y + v1.z + v1.w);
#pragma unroll
    for (int o = 16; o > 0; o >>= 1) s += __shfl_xor_sync(0xffffffffu, s, o);
    if ((t & 31) == 0) red[t >> 5] = s;
    __syncthreads();
    float tot = 0.f;
#pragma unroll
    for (int w = 0; w < 8; w++) tot += red[w];
    float inv = 1.f / tot;

    v0.x *= inv; v0.y *= inv; v0.z *= inv; v0.w *= inv;
    v1.x *= inv; v1.y *= inv; v1.z *= inv; v1.w *= inv;
    if (hout) {
        __half2* h = (__half2*)(hout + (size_t)blockIdx.x * SS);
        h[2 * t]             = __floats2half2_rn(v0.x, v0.y);
        h[2 * t + 1]         = __floats2half2_rn(v0.z, v0.w);
        h[2 * (t + 256)]     = __floats2half2_rn(v1.x, v1.y);
        h[2 * (t + 256) + 1] = __floats2half2_rn(v1.z, v1.w);
    } else {
        row[t] = v0;
        row[t + 256] = v1;
    }
}

// ---------------------------------------------------------------------------
// global_out two-stage (fp32 v)
// ---------------------------------------------------------------------------
__global__ void __launch_bounds__(128) k_gout_part(
    const float* __restrict__ gw, const float* __restrict__ vp, float* __restrict__ part)
{
    int a = blockIdx.x * 128 + threadIdx.x;
    int sc = blockIdx.y, b = blockIdx.z;
    const float* vb = vp + (size_t)b * SS * AD + (size_t)(sc * 128) * AD + a;
    const float* w = gw + b * SS + sc * 128;
    float sum = 0.f;
#pragma unroll 4
    for (int s = 0; s < 128; s++) sum += w[s] * vb[(size_t)s * AD];
    part[((size_t)b * 16 + sc) * AD + a] = sum;
}
__global__ void __launch_bounds__(128) k_gout_red(
    const float* __restrict__ part, float* __restrict__ go)
{
    int a = blockIdx.x * 128 + threadIdx.x;
    int b = blockIdx.y;
    float s = 0.f;
#pragma unroll
    for (int j = 0; j < 16; j++) s += part[((size_t)b * 16 + j) * AD + a];
    go[b * AD + a] = s;
}

// ---------------------------------------------------------------------------
// LayerNorm in-place (rows of DD)
// ---------------------------------------------------------------------------
__global__ void __launch_bounds__(256) k_ln(
    float* __restrict__ y, const float* __restrict__ gamma, const float* __restrict__ beta)
{
    float* row = y + (size_t)blockIdx.x * DD;
    int t = threadIdx.x;
    float v[4], sum = 0.f, sq = 0.f;
#pragma unroll
    for (int i = 0; i < 4; i++) {
        v[i] = row[t + 256 * i];
        sum += v[i];
        sq += v[i] * v[i];
    }
    __shared__ float r1[8], r2[8];
#pragma unroll
    for (int o = 16; o > 0; o >>= 1) {
        sum += __shfl_xor_sync(0xffffffffu, sum, o);
        sq += __shfl_xor_sync(0xffffffffu, sq, o);
    }
    if ((t & 31) == 0) { r1[t >> 5] = sum; r2[t >> 5] = sq; }
    __syncthreads();
    float ts = 0.f, tq = 0.f;
#pragma unroll
    for (int w = 0; w < 8; w++) { ts += r1[w]; tq += r2[w]; }
    float mu = ts * (1.f / DD);
    float var = tq * (1.f / DD) - mu * mu;
    float inv = rsqrtf(var + 1e-5f);
#pragma unroll
    for (int i = 0; i < 4; i++) {
        int c = t + 256 * i;
        row[c] = (v[i] - mu) * inv * gamma[c] + beta[c];
    }
}

// ---------------------------------------------------------------------------
// colmean two-stage (HALF weights -> fp32 partials)
// ---------------------------------------------------------------------------
__global__ void __launch_bounds__(256) k_colmean_part(
    const __half* __restrict__ wts, float* __restrict__ part)
{
    int s = blockIdx.x * 256 + threadIdx.x;
    int qc = blockIdx.y, b = blockIdx.z;
    const __half* base = wts + (size_t)b * SS * SS + (size_t)(qc * 256) * SS + s;
    float sum = 0.f;
#pragma unroll 4
    for (int q = 0; q < 256; q++) sum += __half2float(base[(size_t)q * SS]);
    part[((size_t)b * 8 + qc) * SS + s] = sum;
}
__global__ void __launch_bounds__(256) k_colmean_red(
    const float* __restrict__ part, const float* __restrict__ gw, float* __restrict__ avg)
{
    int s = blockIdx.x * 256 + threadIdx.x;
    int b = blockIdx.y;
    float sum = 0.f;
#pragma unroll
    for (int j = 0; j < 8; j++) sum += part[((size_t)b * 8 + j) * SS + s];
    avg[b * SS + s] = 0.7f * (sum * (1.f / SS)) + 0.3f * gw[b * SS + s];
}

// ---------------------------------------------------------------------------
// context two-stage
// ---------------------------------------------------------------------------
__global__ void __launch_bounds__(256) k_context_part(
    const float* __restrict__ avg, const float* __restrict__ y, float* __restrict__ part)
{
    int d = blockIdx.x * 256 + threadIdx.x;
    int sc = blockIdx.y, b = blockIdx.z;
    const float* yb = y + (size_t)b * SS * DD + (size_t)(sc * 128) * DD + d;
    const float* w = avg + b * SS + sc * 128;
    float sum = 0.f;
#pragma unroll 4
    for (int s = 0; s < 128; s++) sum += w[s] * yb[(size_t)s * DD];
    part[((size_t)b * 16 + sc) * DD + d] = sum;
}
__global__ void __launch_bounds__(256) k_context_red(
    const float* __restrict__ part, float* __restrict__ ctx)
{
    int d = blockIdx.x * 256 + threadIdx.x;
    int b = blockIdx.y;
    float s = 0.f;
#pragma unroll
    for (int j = 0; j < 16; j++) s += part[((size_t)b * 16 + j) * DD + d];
    ctx[b * DD + d] = s;
}

// ---------------------------------------------------------------------------

extern "C" void kernel_launch(void* const* d_in, const int* in_sizes, int n_in,
                              void* d_out, int out_size)
{
    const float* x     = (const float*)d_in[0];
    const float* gc    = (const float*)d_in[1];
    const float* Wq    = (const float*)d_in[2];
    const float* bq    = (const float*)d_in[3];
    const float* Wk    = (const float*)d_in[4];
    const float* bk    = (const float*)d_in[5];
    const float* Wv    = (const float*)d_in[6];
    const float* bv    = (const float*)d_in[7];
    const float* Wo    = (const float*)d_in[8];
    const float* bo    = (const float*)d_in[9];
    const float* gamma = (const float*)d_in[10];
    const float* beta  = (const float*)d_in[11];
    float* outp = (float*)d_out;

    float *pv, *psc, *py, *pgq, *pgs, *pgo, *ppart;
    __half *pxh, *pwqt, *pwkt, *pwvt, *pwot, *pqh, *pkh, *pvth, *pwh, *pwinh;
    cudaGetSymbolAddress((void**)&pv,   g_v);
    cudaGetSymbolAddress((void**)&psc,  g_scores);
    cudaGetSymbolAddress((void**)&py,   g_y);
    cudaGetSymbolAddress((void**)&pgq,  g_gq);
    cudaGetSymbolAddress((void**)&pgs,  g_gs);
    cudaGetSymbolAddress((void**)&pgo,  g_gout);
    cudaGetSymbolAddress((void**)&ppart, g_part);
    cudaGetSymbolAddress((void**)&pxh,  g_xh);
    cudaGetSymbolAddress((void**)&pwqt, g_wqt);
    cudaGetSymbolAddress((void**)&pwkt, g_wkt);
    cudaGetSymbolAddress((void**)&pwvt, g_wvt);
    cudaGetSymbolAddress((void**)&pwot, g_wot);
    cudaGetSymbolAddress((void**)&pqh,  g_qh);
    cudaGetSymbolAddress((void**)&pkh,  g_kh);
    cudaGetSymbolAddress((void**)&pvth, g_vth);
    cudaGetSymbolAddress((void**)&pwh,  g_wh);
    cudaGetSymbolAddress((void**)&pwinh, g_winh);

    const float scl = 1.0f / sqrtf((float)AD);
    const size_t strBSA = (size_t)SS * AD;
    const size_t strBSS = (size_t)SS * SS;

    // 1. x -> half
    k_conv_h<<<(BB * SS * DD) / 1024, 256>>>((const float4*)x, pxh);
    // 2-5. weight transposes (half)
    k_transpose_h<<<dim3(AD / 32, DD / 32, 1), dim3(32, 8)>>>(Wq, pwqt, DD, AD, 0, 0);
    k_transpose_h<<<dim3(AD / 32, DD / 32, 1), dim3(32, 8)>>>(Wk, pwkt, DD, AD, 0, 0);
    k_transpose_h<<<dim3(AD / 32, DD / 32, 1), dim3(32, 8)>>>(Wv, pwvt, DD, AD, 0, 0);
    k_transpose_h<<<dim3(DD / 32, AD / 32, 1), dim3(32, 8)>>>(Wo, pwot, AD, DD, 0, 0);

    // 6-8. Q,K,V projections
    gemm_h<0><<<dim3(AD / 128, (BB * SS) / 128, 1), 128>>>(
        pxh, pwqt, nullptr, pqh, DD, DD, DD, AD, 0, 0, 0, bq, nullptr, 0.f);
    gemm_h<0><<<dim3(AD / 128, (BB * SS) / 128, 1), 128>>>(
        pxh, pwkt, nullptr, pkh, DD, DD, DD, AD, 0, 0, 0, bk, nullptr, 0.f);
    gemm_h<1><<<dim3(AD / 128, (BB * SS) / 128, 1), 128>>>(
        pxh, pwvt, pv, nullptr, DD, DD, DD, AD, 0, 0, 0, bv, nullptr, 0.f);

    // 9. v fp32 [s][a] -> vT half [a][s] per batch
    k_transpose_h<<<dim3(AD / 32, SS / 32, BB), dim3(32, 8)>>>(
        pv, pvth, SS, AD, strBSA, strBSA);

    // 10-11. global query projection
    k_gq_part<<<dim3(AD / 128, 8, BB), 128>>>(gc, Wq, ppart);
    k_gq_red<<<dim3(AD / 128, BB), 128>>>(ppart, bq, pgq);

    // 12. scores = q @ k^T / sqrt(A)
    gemm_h<2><<<dim3(SS / 128, SS / 128, BB), 128>>>(
        pqh, pkh, psc, nullptr, AD, AD, AD, SS, strBSA, strBSA, strBSS,
        nullptr, nullptr, scl);

    // 13. softmax -> half weights only
    k_softmax<<<BB * SS, 256>>>(psc, pwh);

    // 14-15. global scores + softmax (fp32)
    k_gscores<<<(BB * SS) / 32, 256>>>(pkh, pgq, pgs);
    k_softmax<<<BB, 256>>>(pgs, nullptr);

    // 16-17. global_out
    k_gout_part<<<dim3(AD / 128, 16, BB), 128>>>(pgs, pv, ppart);
    k_gout_red<<<dim3(AD / 128, BB), 128>>>(ppart, pgo);

    // 18. win = 0.7*weights@v + 0.3*gout
    gemm_h<3><<<dim3(AD / 128, SS / 128, BB), 128>>>(
        pwh, pvth, nullptr, pwinh, SS, SS, SS, AD, strBSS, strBSA, strBSA,
        pgo, nullptr, 0.f);

    // 19. y = x + win @ Wo + bo
    gemm_h<4><<<dim3(DD / 128, (BB * SS) / 128, 1), 128>>>(
        pwinh, pwot, py, nullptr, AD, AD, AD, DD, 0, 0, 0, bo, x, 0.f);

    // 20. LayerNorm
    k_ln<<<BB * SS, 256>>>(py, gamma, beta);

    // 21-22. avg_w (half weights)
    k_colmean_part<<<dim3(SS / 256, 8, BB), 256>>>(pwh, ppart);
    k_colmean_red<<<dim3(SS / 256, BB), 256>>>(ppart, pgs, outp + BB * DD);

    // 23-24. context
    k_context_part<<<dim3(DD / 256, 16, BB), 256>>>(outp + BB * DD, py, ppart);
    k_context_red<<<dim3(DD / 256, BB), 256>>>(ppart, outp);
}

// round 10
// speedup vs baseline: 5.5662x; 1.0510x over previous
#include <cuda_runtime.h>
#include <cuda_fp16.h>
#include <math.h>
#include <stdint.h>

// Problem constants
#define BB 8
#define SS 2048
#define DD 1024
#define AD 512
#define NQKV 1536   // 3*AD concatenated q|k|v output columns

// ---------------------------------------------------------------------------
// Scratch (__device__ globals; allocation-free rule)
// ---------------------------------------------------------------------------
__device__ float  g_y[BB * SS * DD];
__device__ float  g_gq[BB * AD];
__device__ float  g_gs[BB * SS];
__device__ float  g_gout[BB * AD];
__device__ float  g_part[BB * 16 * SS];
__device__ float  g_bqkv[NQKV];

__device__ __half g_xh[BB * SS * DD];                 // half x
__device__ __half g_wqkvt[NQKV * DD];                 // [Wq|Wk|Wv]^T half [1536][1024]
__device__ __half g_wot[DD * AD];                     // Wo^T half [D][A]
__device__ __half g_qkv[(size_t)BB * SS * NQKV];      // q|k|v interleaved [b][s][1536]
__device__ __half g_vth[BB * SS * AD];                // V^T half [b][a][s]
__device__ __half g_wh[(size_t)BB * SS * SS];         // half scores -> softmax weights
__device__ __half g_winh[BB * SS * AD];

// ---------------------------------------------------------------------------
// fp16 tensor-core GEMM, all-NT: C[m][n] = sum_k A[m][k] * B[n][k]
// Block 128x128, K-chunk 32, 128 threads (4 warps 2x2, warp tile 64x64).
// mma.sync.m16n8k16 fp32-accum, ldmatrix frag loads, 3-stage cp.async.
// EPI: 0 half out +e0[n]; 2 half out *scale;
//      3 half out 0.7*acc+0.3*e0[z*AD+n]; 4 f32 out +e0[n]+e1[m*ldc+n]
// ---------------------------------------------------------------------------
#define HSTR 40                       // row stride in halves (80 B)
#define STG_H (128 * HSTR)            // halves per stage per operand
#define GH_SMEM (3 * STG_H * 2 * 2)   // 61440 B (3 stages, A+B, 2B/half)

__device__ __forceinline__ void cp16(void* s, const void* g) {
    uint32_t sa = (uint32_t)__cvta_generic_to_shared(s);
    asm volatile("cp.async.cg.shared.global [%0], [%1], 16;\n" :: "r"(sa), "l"(g));
}
#define LDSM4(r0, r1, r2, r3, a) \
    asm volatile("ldmatrix.sync.aligned.m8n8.x4.shared.b16 {%0,%1,%2,%3}, [%4];" \
                 : "=r"(r0), "=r"(r1), "=r"(r2), "=r"(r3) : "r"(a))

template <int EPI>
__global__ void __launch_bounds__(128, 3) gemm_h(
    const __half* __restrict__ Am, const __half* __restrict__ Bm,
    float* __restrict__ Cf, __half* __restrict__ Ch,
    int K, int lda, int ldb, int ldc,
    size_t sA, size_t sB, size_t sC,
    const float* __restrict__ e0, const float* __restrict__ e1, float scale)
{
    extern __shared__ __half sh[];
    __half* As = sh;                 // 3 stages x 128 x HSTR
    __half* Bs = sh + 3 * STG_H;

    const __half* Ap = Am + (size_t)blockIdx.z * sA;
    const __half* Bp = Bm + (size_t)blockIdx.z * sB;

    const int tid = threadIdx.x;
    const int wid = tid >> 5;
    const int lane = tid & 31;
    const int wm = wid >> 1;
    const int wn = wid & 1;
    const int g = lane >> 2;
    const int t = lane & 3;
    const int m0 = blockIdx.y * 128;
    const int n0 = blockIdx.x * 128;

    const int lrow = lane & 15;
    const int lcol = (lane >> 4) << 3;
    const uint32_t sAb = (uint32_t)__cvta_generic_to_shared(As);
    const uint32_t sBb = (uint32_t)__cvta_generic_to_shared(Bs);
    const uint32_t stageBytes = STG_H * 2;

    float acc[4][8][4];
#pragma unroll
    for (int i = 0; i < 4; i++)
#pragma unroll
        for (int j = 0; j < 8; j++)
#pragma unroll
            for (int c = 0; c < 4; c++) acc[i][j][c] = 0.f;

    auto copy_stage = [&](int st, int k0) {
#pragma unroll
        for (int i = 0; i < 4; i++) {
            int c = tid + 128 * i;
            int row = c >> 2, off = (c & 3) << 3;
            cp16(&As[st * STG_H + row * HSTR + off],
                 Ap + (size_t)(m0 + row) * lda + k0 + off);
        }
#pragma unroll
        for (int i = 0; i < 4; i++) {
            int c = tid + 128 * i;
            int row = c >> 2, off = (c & 3) << 3;
            cp16(&Bs[st * STG_H + row * HSTR + off],
                 Bp + (size_t)(n0 + row) * ldb + k0 + off);
        }
    };

    const int nk = K / 32;
    copy_stage(0, 0);
    asm volatile("cp.async.commit_group;\n");
    copy_stage(1, 32);
    asm volatile("cp.async.commit_group;\n");

    int cur = 0;
    for (int kt = 0; kt < nk; kt++) {
        if (kt + 1 < nk) asm volatile("cp.async.wait_group 1;\n");
        else             asm volatile("cp.async.wait_group 0;\n");
        __syncthreads();
        if (kt + 2 < nk) {
            int nx = cur + 2; if (nx >= 3) nx -= 3;
            copy_stage(nx, (kt + 2) * 32);
            asm volatile("cp.async.commit_group;\n");
        }
        uint32_t aBase = sAb + cur * stageBytes + ((wm * 64 + lrow) * HSTR + lcol) * 2;
        uint32_t bBase = sBb + cur * stageBytes + ((wn * 64 + lrow) * HSTR + lcol) * 2;
#pragma unroll
        for (int ks = 0; ks < 2; ks++) {
            const int kb = ks * 16;
            uint32_t afr[4][4];
#pragma unroll
            for (int mt = 0; mt < 4; mt++)
                LDSM4(afr[mt][0], afr[mt][1], afr[mt][2], afr[mt][3],
                      aBase + (mt * 16 * HSTR + kb) * 2);
#pragma unroll
            for (int p = 0; p < 4; p++) {
                uint32_t b00, b01, b10, b11;
                LDSM4(b00, b01, b10, b11, bBase + (p * 16 * HSTR + kb) * 2);
#pragma unroll
                for (int h = 0; h < 2; h++) {
                    int nt = p * 2 + h;
                    uint32_t b0 = h ? b01 : b00;
                    uint32_t b1 = h ? b11 : b10;
#pragma unroll
                    for (int mt = 0; mt < 4; mt++) {
                        asm volatile(
                            "mma.sync.aligned.m16n8k16.row.col.f32.f16.f16.f32 "
                            "{%0,%1,%2,%3}, {%4,%5,%6,%7}, {%8,%9}, {%0,%1,%2,%3};\n"
                            : "+f"(acc[mt][nt][0]), "+f"(acc[mt][nt][1]),
                              "+f"(acc[mt][nt][2]), "+f"(acc[mt][nt][3])
                            : "r"(afr[mt][0]), "r"(afr[mt][1]),
                              "r"(afr[mt][2]), "r"(afr[mt][3]),
                              "r"(b0), "r"(b1));
                    }
                }
            }
        }
        if (++cur == 3) cur = 0;
    }

    // Epilogue (C frag: c0,c1 = row g cols 2t,2t+1; c2,c3 = row g+8)
#pragma unroll
    for (int mt = 0; mt < 4; mt++) {
#pragma unroll
        for (int nt = 0; nt < 8; nt++) {
            int row = m0 + wm * 64 + mt * 16 + g;
            int col = n0 + wn * 64 + nt * 8 + 2 * t;
#pragma unroll
            for (int h = 0; h < 2; h++) {
                int r = row + h * 8;
                float v0 = acc[mt][nt][h * 2 + 0];
                float v1 = acc[mt][nt][h * 2 + 1];
                if (EPI == 0) {
                    v0 += e0[col]; v1 += e0[col + 1];
                    __half* Cp = Ch + (size_t)blockIdx.z * sC;
                    *(__half2*)&Cp[(size_t)r * ldc + col] = __floats2half2_rn(v0, v1);
                } else if (EPI == 2) {
                    __half* Cp = Ch + (size_t)blockIdx.z * sC;
                    *(__half2*)&Cp[(size_t)r * ldc + col] =
                        __floats2half2_rn(v0 * scale, v1 * scale);
                } else if (EPI == 3) {
                    v0 = 0.7f * v0 + 0.3f * e0[blockIdx.z * AD + col];
                    v1 = 0.7f * v1 + 0.3f * e0[blockIdx.z * AD + col + 1];
                    __half* Cp = Ch + (size_t)blockIdx.z * sC;
                    *(__half2*)&Cp[(size_t)r * ldc + col] = __floats2half2_rn(v0, v1);
                } else {
                    v0 += e0[col]     + e1[(size_t)r * ldc + col];
                    v1 += e0[col + 1] + e1[(size_t)r * ldc + col + 1];
                    float* Cp = Cf + (size_t)blockIdx.z * sC;
                    *(float2*)&Cp[(size_t)r * ldc + col] = make_float2(v0, v1);
                }
            }
        }
    }
}

// ---------------------------------------------------------------------------
// Elementwise f32 -> f16
// ---------------------------------------------------------------------------
__global__ void __launch_bounds__(256) k_conv_h(const float4* __restrict__ in,
                                               __half* __restrict__ out)
{
    int i = blockIdx.x * 256 + threadIdx.x;
    float4 v = in[i];
    __half2* o = (__half2*)(out + (size_t)i * 4);
    o[0] = __floats2half2_rn(v.x, v.y);
    o[1] = __floats2half2_rn(v.z, v.w);
}

// ---------------------------------------------------------------------------
// Transpose + convert: src f32 [R][C] -> dst half [C][R].  block (32,8)
// ---------------------------------------------------------------------------
__global__ void k_transpose_h(const float* __restrict__ src, __half* __restrict__ dst,
                              int R, int C)
{
    __shared__ float t[32][33];
    int c0 = blockIdx.x * 32, r0 = blockIdx.y * 32;
    int tx = threadIdx.x, ty = threadIdx.y;
#pragma unroll
    for (int i = 0; i < 32; i += 8)
        t[ty + i][tx] = src[(size_t)(r0 + ty + i) * C + c0 + tx];
    __syncthreads();
#pragma unroll
    for (int i = 0; i < 32; i += 8)
        dst[(size_t)(c0 + ty + i) * R + r0 + tx] = __float2half(t[tx][ty + i]);
}

// ---------------------------------------------------------------------------
// Half transpose: src half [R][srcLd] (+batch) -> dst half [C][R] (+batch)
// ---------------------------------------------------------------------------
__global__ void k_transpose_hh(const __half* __restrict__ src, __half* __restrict__ dst,
                               int R, int C, int srcLd, size_t sSrc, size_t sDst)
{
    __shared__ __half t[32][34];
    src += (size_t)blockIdx.z * sSrc;
    dst += (size_t)blockIdx.z * sDst;
    int c0 = blockIdx.x * 32, r0 = blockIdx.y * 32;
    int tx = threadIdx.x, ty = threadIdx.y;
#pragma unroll
    for (int i = 0; i < 32; i += 8)
        t[ty + i][tx] = src[(size_t)(r0 + ty + i) * srcLd + c0 + tx];
    __syncthreads();
#pragma unroll
    for (int i = 0; i < 32; i += 8)
        dst[(size_t)(c0 + ty + i) * R + r0 + tx] = t[tx][ty + i];
}

// ---------------------------------------------------------------------------
// Concatenate the three bias vectors into g_bqkv
// ---------------------------------------------------------------------------
__global__ void __launch_bounds__(256) k_concat_bias(
    const float* __restrict__ bq, const float* __restrict__ bk,
    const float* __restrict__ bv, float* __restrict__ out)
{
    int i = blockIdx.x * 256 + threadIdx.x;
    float v = (i < AD) ? bq[i] : (i < 2 * AD) ? bk[i - AD] : bv[i - 2 * AD];
    out[i] = v;
}

// ---------------------------------------------------------------------------
// gq two-stage (fp32 Wq)
// ---------------------------------------------------------------------------
__global__ void __launch_bounds__(128) k_gq_part(
    const float* __restrict__ gc, const float* __restrict__ W, float* __restrict__ part)
{
    int a = blockIdx.x * 128 + threadIdx.x;
    int dc = blockIdx.y, b = blockIdx.z;
    const float* gv = gc + (size_t)b * DD + dc * 128;
    const float* Wp = W + (size_t)(dc * 128) * AD + a;
    float s = 0.f;
#pragma unroll 4
    for (int d = 0; d < 128; d++) s += gv[d] * Wp[(size_t)d * AD];
    part[((size_t)b * 8 + dc) * AD + a] = s;
}
__global__ void __launch_bounds__(128) k_gq_red(
    const float* __restrict__ part, const float* __restrict__ bias, float* __restrict__ gq)
{
    int a = blockIdx.x * 128 + threadIdx.x;
    int b = blockIdx.y;
    float s = bias[a];
#pragma unroll
    for (int j = 0; j < 8; j++) s += part[((size_t)b * 8 + j) * AD + a];
    gq[b * AD + a] = s;
}

// ---------------------------------------------------------------------------
// gscores[b,s] = dot(gq[b,:], k[b,s,:]) / sqrt(AD)  (k inside qkv, stride 1536)
// ---------------------------------------------------------------------------
__global__ void __launch_bounds__(256) k_gscores(
    const __half* __restrict__ qkv, const float* __restrict__ gq, float* __restrict__ gs)
{
    int t = threadIdx.x;
    int key = blockIdx.x * 32 + (t >> 3);
    int lane = t & 7;
    int b = key / SS;
    int s = key % SS;
    const __half* krow = qkv + (size_t)key * NQKV + AD;
    const float* q = gq + b * AD;
    float sum = 0.f;
    for (int a = lane; a < AD; a += 8) sum += __half2float(krow[a]) * q[a];
#pragma unroll
    for (int o = 4; o > 0; o >>= 1) sum += __shfl_down_sync(0xffffffffu, sum, o, 8);
    if (lane == 0) gs[b * SS + s] = sum * rsqrtf((float)AD);
}

// ---------------------------------------------------------------------------
// In-place half softmax, rows of SS=2048. 256 threads; 8 halves/thread.
// ---------------------------------------------------------------------------
__global__ void __launch_bounds__(256) k_softmax_h(__half* __restrict__ data)
{
    uint4* row = (uint4*)(data + (size_t)blockIdx.x * SS);
    int t = threadIdx.x;
    uint4 u = row[t];
    __half2 h[4];
    memcpy(h, &u, 16);
    float v[8];
#pragma unroll
    for (int i = 0; i < 4; i++) {
        float2 f = __half22float2(h[i]);
        v[2 * i] = f.x; v[2 * i + 1] = f.y;
    }
    __shared__ float red[8];

    float m = v[0];
#pragma unroll
    for (int i = 1; i < 8; i++) m = fmaxf(m, v[i]);
#pragma unroll
    for (int o = 16; o > 0; o >>= 1) m = fmaxf(m, __shfl_xor_sync(0xffffffffu, m, o));
    if ((t & 31) == 0) red[t >> 5] = m;
    __syncthreads();
    m = red[0];
#pragma unroll
    for (int w = 1; w < 8; w++) m = fmaxf(m, red[w]);
    __syncthreads();

    float s = 0.f;
#pragma unroll
    for (int i = 0; i < 8; i++) { v[i] = __expf(v[i] - m); s += v[i]; }
#pragma unroll
    for (int o = 16; o > 0; o >>= 1) s += __shfl_xor_sync(0xffffffffu, s, o);
    if ((t & 31) == 0) red[t >> 5] = s;
    __syncthreads();
    float tot = 0.f;
#pragma unroll
    for (int w = 0; w < 8; w++) tot += red[w];
    float inv = 1.f / tot;

#pragma unroll
    for (int i = 0; i < 4; i++)
        h[i] = __floats2half2_rn(v[2 * i] * inv, v[2 * i + 1] * inv);
    memcpy(&u, h, 16);
    row[t] = u;
}

// ---------------------------------------------------------------------------
// fp32 softmax (for the tiny global-scores rows)
// ---------------------------------------------------------------------------
__global__ void __launch_bounds__(256) k_softmax_f(float* __restrict__ data)
{
    float4* row = (float4*)(data + (size_t)blockIdx.x * SS);
    int t = threadIdx.x;
    float4 v0 = row[t];
    float4 v1 = row[t + 256];
    __shared__ float red[8];

    float m = fmaxf(fmaxf(fmaxf(v0.x, v0.y), fmaxf(v0.z, v0.w)),
                    fmaxf(fmaxf(v1.x, v1.y), fmaxf(v1.z, v1.w)));
#pragma unroll
    for (int o = 16; o > 0; o >>= 1) m = fmaxf(m, __shfl_xor_sync(0xffffffffu, m, o));
    if ((t & 31) == 0) red[t >> 5] = m;
    __syncthreads();
    m = red[0];
#pragma unroll
    for (int w = 1; w < 8; w++) m = fmaxf(m, red[w]);
    __syncthreads();

    v0.x = __expf(v0.x - m); v0.y = __expf(v0.y - m);
    v0.z = __expf(v0.z - m); v0.w = __expf(v0.w - m);
    v1.x = __expf(v1.x - m); v1.y = __expf(v1.y - m);
    v1.z = __expf(v1.z - m); v1.w = __expf(v1.w - m);

    float s = (v0.x + v0.y + v0.z + v0.w) + (v1.x + v1.y + v1.z + v1.w);
#pragma unroll
    for (int o = 16; o > 0; o >>= 1) s += __shfl_xor_sync(0xffffffffu, s, o);
    if ((t & 31) == 0) red[t >> 5] = s;
    __syncthreads();
    float tot = 0.f;
#pragma unroll
    for (int w = 0; w < 8; w++) tot += red[w];
    float inv = 1.f / tot;

    v0.x *= inv; v0.y *= inv; v0.z *= inv; v0.w *= inv;
    v1.x *= inv; v1.y *= inv; v1.z *= inv; v1.w *= inv;
    row[t] = v0;
    row[t + 256] = v1;
}

// ---------------------------------------------------------------------------
// global_out two-stage (half v inside qkv, stride 1536)
// ---------------------------------------------------------------------------
__global__ void __launch_bounds__(128) k_gout_part(
    const float* __restrict__ gw, const __half* __restrict__ qkv, float* __restrict__ part)
{
    int a = blockIdx.x * 128 + threadIdx.x;
    int sc = blockIdx.y, b = blockIdx.z;
    const __half* vb = qkv + (size_t)b * SS * NQKV + (size_t)(sc * 128) * NQKV + 2 * AD + a;
    const float* w = gw + b * SS + sc * 128;
    float sum = 0.f;
#pragma unroll 4
    for (int s = 0; s < 128; s++) sum += w[s] * __half2float(vb[(size_t)s * NQKV]);
    part[((size_t)b * 16 + sc) * AD + a] = sum;
}
__global__ void __launch_bounds__(128) k_gout_red(
    const float* __restrict__ part, float* __restrict__ go)
{
    int a = blockIdx.x * 128 + threadIdx.x;
    int b = blockIdx.y;
    float s = 0.f;
#pragma unroll
    for (int j = 0; j < 16; j++) s += part[((size_t)b * 16 + j) * AD + a];
    go[b * AD + a] = s;
}

// ---------------------------------------------------------------------------
// LayerNorm in-place (rows of DD)
// ---------------------------------------------------------------------------
__global__ void __launch_bounds__(256) k_ln(
    float* __restrict__ y, const float* __restrict__ gamma, const float* __restrict__ beta)
{
    float* row = y + (size_t)blockIdx.x * DD;
    int t = threadIdx.x;
    float v[4], sum = 0.f, sq = 0.f;
#pragma unroll
    for (int i = 0; i < 4; i++) {
        v[i] = row[t + 256 * i];
        sum += v[i];
        sq += v[i] * v[i];
    }
    __shared__ float r1[8], r2[8];
#pragma unroll
    for (int o = 16; o > 0; o >>= 1) {
        sum += __shfl_xor_sync(0xffffffffu, sum, o);
        sq += __shfl_xor_sync(0xffffffffu, sq, o);
    }
    if ((t & 31) == 0) { r1[t >> 5] = sum; r2[t >> 5] = sq; }
    __syncthreads();
    float ts = 0.f, tq = 0.f;
#pragma unroll
    for (int w = 0; w < 8; w++) { ts += r1[w]; tq += r2[w]; }
    float mu = ts * (1.f / DD);
    float var = tq * (1.f / DD) - mu * mu;
    float inv = rsqrtf(var + 1e-5f);
#pragma unroll
    for (int i = 0; i < 4; i++) {
        int c = t + 256 * i;
        row[c] = (v[i] - mu) * inv * gamma[c] + beta[c];
    }
}

// ---------------------------------------------------------------------------
// colmean two-stage (HALF weights -> fp32 partials)
// ---------------------------------------------------------------------------
__global__ void __launch_bounds__(256) k_colmean_part(
    const __half* __restrict__ wts, float* __restrict__ part)
{
    int s = blockIdx.x * 256 + threadIdx.x;
    int qc = blockIdx.y, b = blockIdx.z;
    const __half* base = wts + (size_t)b * SS * SS + (size_t)(qc * 256) * SS + s;
    float sum = 0.f;
#pragma unroll 4
    for (int q = 0; q < 256; q++) sum += __half2float(base[(size_t)q * SS]);
    part[((size_t)b * 8 + qc) * SS + s] = sum;
}
__global__ void __launch_bounds__(256) k_colmean_red(
    const float* __restrict__ part, const float* __restrict__ gw, float* __restrict__ avg)
{
    int s = blockIdx.x * 256 + threadIdx.x;
    int b = blockIdx.y;
    float sum = 0.f;
#pragma unroll
    for (int j = 0; j < 8; j++) sum += part[((size_t)b * 8 + j) * SS + s];
    avg[b * SS + s] = 0.7f * (sum * (1.f / SS)) + 0.3f * gw[b * SS + s];
}

// ---------------------------------------------------------------------------
// context two-stage
// ---------------------------------------------------------------------------
__global__ void __launch_bounds__(256) k_context_part(
    const float* __restrict__ avg, const float* __restrict__ y, float* __restrict__ part)
{
    int d = blockIdx.x * 256 + threadIdx.x;
    int sc = blockIdx.y, b = blockIdx.z;
    const float* yb = y + (size_t)b * SS * DD + (size_t)(sc * 128) * DD + d;
    const float* w = avg + b * SS + sc * 128;
    float sum = 0.f;
#pragma unroll 4
    for (int s = 0; s < 128; s++) sum += w[s] * yb[(size_t)s * DD];
    part[((size_t)b * 16 + sc) * DD + d] = sum;
}
__global__ void __launch_bounds__(256) k_context_red(
    const float* __restrict__ part, float* __restrict__ ctx)
{
    int d = blockIdx.x * 256 + threadIdx.x;
    int b = blockIdx.y;
    float s = 0.f;
#pragma unroll
    for (int j = 0; j < 16; j++) s += part[((size_t)b * 16 + j) * DD + d];
    ctx[b * DD + d] = s;
}

// ---------------------------------------------------------------------------

extern "C" void kernel_launch(void* const* d_in, const int* in_sizes, int n_in,
                              void* d_out, int out_size)
{
    const float* x     = (const float*)d_in[0];
    const float* gc    = (const float*)d_in[1];
    const float* Wq    = (const float*)d_in[2];
    const float* bq    = (const float*)d_in[3];
    const float* Wk    = (const float*)d_in[4];
    const float* bk    = (const float*)d_in[5];
    const float* Wv    = (const float*)d_in[6];
    const float* bv    = (const float*)d_in[7];
    const float* Wo    = (const float*)d_in[8];
    const float* bo    = (const float*)d_in[9];
    const float* gamma = (const float*)d_in[10];
    const float* beta  = (const float*)d_in[11];
    float* outp = (float*)d_out;

    float *py, *pgq, *pgs, *pgo, *ppart, *pbqkv;
    __half *pxh, *pwqkvt, *pwot, *pqkv, *pvth, *pwh, *pwinh;
    cudaGetSymbolAddress((void**)&py,    g_y);
    cudaGetSymbolAddress((void**)&pgq,   g_gq);
    cudaGetSymbolAddress((void**)&pgs,   g_gs);
    cudaGetSymbolAddress((void**)&pgo,   g_gout);
    cudaGetSymbolAddress((void**)&ppart, g_part);
    cudaGetSymbolAddress((void**)&pbqkv, g_bqkv);
    cudaGetSymbolAddress((void**)&pxh,   g_xh);
    cudaGetSymbolAddress((void**)&pwqkvt, g_wqkvt);
    cudaGetSymbolAddress((void**)&pwot,  g_wot);
    cudaGetSymbolAddress((void**)&pqkv,  g_qkv);
    cudaGetSymbolAddress((void**)&pvth,  g_vth);
    cudaGetSymbolAddress((void**)&pwh,   g_wh);
    cudaGetSymbolAddress((void**)&pwinh, g_winh);

    cudaFuncSetAttribute(gemm_h<0>, cudaFuncAttributeMaxDynamicSharedMemorySize, GH_SMEM);
    cudaFuncSetAttribute(gemm_h<2>, cudaFuncAttributeMaxDynamicSharedMemorySize, GH_SMEM);
    cudaFuncSetAttribute(gemm_h<3>, cudaFuncAttributeMaxDynamicSharedMemorySize, GH_SMEM);
    cudaFuncSetAttribute(gemm_h<4>, cudaFuncAttributeMaxDynamicSharedMemorySize, GH_SMEM);

    const float scl = 1.0f / sqrtf((float)AD);
    const size_t strQKV = (size_t)SS * NQKV;
    const size_t strBSA = (size_t)SS * AD;
    const size_t strBSS = (size_t)SS * SS;

    // 1. x -> half ; bias concat
    k_conv_h<<<(BB * SS * DD) / 1024, 256>>>((const float4*)x, pxh);
    k_concat_bias<<<NQKV / 256, 256>>>(bq, bk, bv, pbqkv);
    // 2-5. weight transposes (half) into concatenated [1536][1024] + Wo^T
    k_transpose_h<<<dim3(AD / 32, DD / 32), dim3(32, 8)>>>(Wq, pwqkvt, DD, AD);
    k_transpose_h<<<dim3(AD / 32, DD / 32), dim3(32, 8)>>>(Wk, pwqkvt + (size_t)AD * DD, DD, AD);
    k_transpose_h<<<dim3(AD / 32, DD / 32), dim3(32, 8)>>>(Wv, pwqkvt + (size_t)2 * AD * DD, DD, AD);
    k_transpose_h<<<dim3(DD / 32, AD / 32), dim3(32, 8)>>>(Wo, pwot, AD, DD);

    // 6. fused QKV projection: [16384,1024] x [1536,1024]^T -> qkv half
    gemm_h<0><<<dim3(NQKV / 128, (BB * SS) / 128, 1), 128, GH_SMEM>>>(
        pxh, pwqkvt, nullptr, pqkv, DD, DD, DD, NQKV, 0, 0, 0, pbqkv, nullptr, 0.f);

    // 7. v (half, inside qkv) -> vT half [a][s] per batch
    k_transpose_hh<<<dim3(AD / 32, SS / 32, BB), dim3(32, 8)>>>(
        pqkv + 2 * AD, pvth, SS, AD, NQKV, strQKV, strBSA);

    // 8-9. global query projection (fp32)
    k_gq_part<<<dim3(AD / 128, 8, BB), 128>>>(gc, Wq, ppart);
    k_gq_red<<<dim3(AD / 128, BB), 128>>>(ppart, bq, pgq);

    // 10. scores = q @ k^T / sqrt(A)  -> half
    gemm_h<2><<<dim3(SS / 128, SS / 128, BB), 128, GH_SMEM>>>(
        pqkv, pqkv + AD, nullptr, pwh, AD, NQKV, NQKV, SS, strQKV, strQKV, strBSS,
        nullptr, nullptr, scl);

    // 11. softmax in place on half scores
    k_softmax_h<<<BB * SS, 256>>>(pwh);

    // 12-13. global scores + softmax (fp32)
    k_gscores<<<(BB * SS) / 32, 256>>>(pqkv, pgq, pgs);
    k_softmax_f<<<BB, 256>>>(pgs);

    // 14-15. global_out (half v)
    k_gout_part<<<dim3(AD / 128, 16, BB), 128>>>(pgs, pqkv, ppart);
    k_gout_red<<<dim3(AD / 128, BB), 128>>>(ppart, pgo);

    // 16. win = 0.7*weights@v + 0.3*gout
    gemm_h<3><<<dim3(AD / 128, SS / 128, BB), 128, GH_SMEM>>>(
        pwh, pvth, nullptr, pwinh, SS, SS, SS, AD, strBSS, strBSA, strBSA,
        pgo, nullptr, 0.f);

    // 17. y = x + win @ Wo + bo
    gemm_h<4><<<dim3(DD / 128, (BB * SS) / 128, 1), 128, GH_SMEM>>>(
        pwinh, pwot, py, nullptr, AD, AD, AD, DD, 0, 0, 0, bo, x, 0.f);

    // 18. LayerNorm
    k_ln<<<BB * SS, 256>>>(py, gamma, beta);

    // 19-20. avg_w (half weights)
    k_colmean_part<<<dim3(SS / 256, 8, BB), 256>>>(pwh, ppart);
    k_colmean_red<<<dim3(SS / 256, BB), 256>>>(ppart, pgs, outp + BB * DD);

    // 21-22. context
    k_context_part<<<dim3(DD / 256, 16, BB), 256>>>(outp + BB * DD, py, ppart);
    k_context_red<<<dim3(DD / 256, BB), 256>>>(ppart, outp);
}